// round 12
// baseline (speedup 1.0000x reference)
#include <cuda_runtime.h>

#define SEQ    512
#define NROW   2048
#define NPAIR  1024
#define NELEM  (NROW*64)
#define MAXB   512

typedef unsigned long long u64;

// ---------------- f32x2 helpers ----------------
__device__ __forceinline__ u64 ffma2(u64 a, u64 b, u64 c) {
    u64 d; asm("fma.rn.f32x2 %0, %1, %2, %3;" : "=l"(d) : "l"(a), "l"(b), "l"(c)); return d;
}
__device__ __forceinline__ u64 mul2(u64 a, u64 b) {
    u64 d; asm("mul.rn.f32x2 %0, %1, %2;" : "=l"(d) : "l"(a), "l"(b)); return d;
}
__device__ __forceinline__ u64 add2(u64 a, u64 b) {
    u64 d; asm("add.rn.f32x2 %0, %1, %2;" : "=l"(d) : "l"(a), "l"(b)); return d;
}
__device__ __forceinline__ u64 dup2(float x) {
    u64 d; asm("mov.b64 %0, {%1, %1};" : "=l"(d) : "f"(x)); return d;
}
__device__ __forceinline__ u64 pack2(float x, float y) {
    u64 d; asm("mov.b64 %0, {%1, %2};" : "=l"(d) : "f"(x), "f"(y)); return d;
}
__device__ __forceinline__ float2 unpk(u64 a) {
    float2 f; asm("mov.b64 {%0, %1}, %2;" : "=f"(f.x), "=f"(f.y) : "l"(a)); return f;
}
__device__ __forceinline__ float ex2f(float x) {
    float r; asm("ex2.approx.f32 %0, %1;" : "=f"(r) : "f"(x)); return r;
}
__device__ __forceinline__ u64 relu2(u64 a) {
    float2 f = unpk(a); return pack2(fmaxf(f.x, 0.f), fmaxf(f.y, 0.f));
}

// ---------------- device scratch ----------------
__device__ float g_q [NELEM];          // [B,H,S,8]
__device__ float g_kT[NELEM];          // [B,H,8,S]  pre-scaled by 1/sqrt(8)*log2e
__device__ float g_v [NELEM];          // [B,H,S,8]
__device__ u64 g_yp [NPAIR*64];        // y  packed: [pair][col]
__device__ u64 g_ysp[NPAIR*64];        // ys packed
__device__ u64 g_kp [6][NPAIR*64];     // k stages packed
__device__ u64 g_app[NPAIR*64];        // attn out packed [pair][h*8+d]

// duplicated-lane weights: [q|k|v|o](4x4096) + W1(16384) + W2(16384)
#define WD_Q  0
#define WD_K  4096
#define WD_V  8192
#define WD_O  12288
#define WD_1  16384
#define WD_2  32768
#define WD_N  49152
__device__ u64 g_Wd[WD_N];

__device__ unsigned          g_cnt;
__device__ volatile unsigned g_gen;

__constant__ float d_C[6][5] = {
    {0.f,0.f,0.f,0.f,0.f},
    {(float)(0.25*0.25), 0.f,0.f,0.f,0.f},
    {(float)(0.25*3.0/32.0), (float)(0.25*9.0/32.0), 0.f,0.f,0.f},
    {(float)(0.25*1932.0/2197.0), (float)(0.25*-7200.0/2197.0),
     (float)(0.25*7296.0/2197.0), 0.f,0.f},
    {(float)(0.25*439.0/216.0), (float)(0.25*-8.0),
     (float)(0.25*3680.0/513.0), (float)(0.25*-845.0/4104.0), 0.f},
    {(float)(0.25*-8.0/27.0), (float)(0.25*2.0),
     (float)(0.25*-3544.0/2565.0), (float)(0.25*1859.0/4104.0),
     (float)(0.25*-11.0/40.0)}
};
__constant__ float d_B[6] = {
    (float)(0.25*16.0/135.0), 0.f,
    (float)(0.25*6656.0/12825.0),
    (float)(0.25*28561.0/56430.0),
    (float)(0.25*-9.0/50.0),
    (float)(0.25*2.0/55.0)
};

// ---------------- grid barrier (atomic counter) ----------------
__device__ __forceinline__ void gsync(unsigned& gen) {
    __syncthreads();
    if (threadIdx.x == 0) {
        __threadfence();
        if (atomicAdd(&g_cnt, 1u) == gridDim.x - 1) {
            g_cnt = 0;
            __threadfence();
            g_gen = gen + 1;
        } else {
            while (g_gen == gen) { }
            __threadfence();
        }
    }
    __syncthreads();
    gen++;
}

// ---------------- packed GEMM partial (dup'd weights) ----------------
__device__ __forceinline__ void gemm_partial(
        const u64* __restrict__ Wd, int wstride, int colbase,
        const u64* __restrict__ act, int rowlen, int pq2,
        int k0, int kn, u64* acc) {
    const u64* a0 = act + (2 * pq2) * rowlen;
    const u64* a1 = a0 + rowlen;
#pragma unroll 4
    for (int k = k0; k < k0 + kn; k++) {
        const u64* wp = Wd + k * wstride + colbase;
        ulonglong2 w01 = *(const ulonglong2*)wp;
        ulonglong2 w23 = *(const ulonglong2*)(wp + 2);
        u64 z0 = a0[k], z1 = a1[k];
        acc[0] = ffma2(z0, w01.x, acc[0]); acc[1] = ffma2(z1, w01.x, acc[1]);
        acc[2] = ffma2(z0, w01.y, acc[2]); acc[3] = ffma2(z1, w01.y, acc[3]);
        acc[4] = ffma2(z0, w23.x, acc[4]); acc[5] = ffma2(z1, w23.x, acc[5]);
        acc[6] = ffma2(z0, w23.y, acc[6]); acc[7] = ffma2(z1, w23.y, acc[7]);
    }
}

// 8-way k-group gather for 64-col GEMMs (writers tid = c4 + 16*pq2 + 32*kq)
__device__ __forceinline__ u64 gather8(const u64* __restrict__ red, int base, int j) {
    u64 s = red[base * 9 + j];
#pragma unroll
    for (int kq = 1; kq < 8; kq++)
        s = add2(s, red[(base + 32 * kq) * 9 + j]);
    return s;
}

// ---------------- QKV: 3 sequential 64-col GEMMs from packed ys ----------------
// K is written PRE-SCALED by 1/sqrt(8)*log2(e) (K only feeds scores).
__device__ __forceinline__ void qkv_mats(
        int unit, const u64* __restrict__ ys_p, u64* __restrict__ red,
        const float* __restrict__ bq, const float* __restrict__ bk,
        const float* __restrict__ bv) {
    const int tid = threadIdx.x;
    const int c4 = tid & 15, pq2 = (tid >> 4) & 1, kq = tid >> 5;
    const int fc = tid & 63, fp = tid >> 6;
    const int row0 = unit * 8 + 2 * fp;
    const int b = row0 >> 9, s = row0 & 511;
    const int h = fc >> 3, dd = fc & 7;
    const int gbase = (fc >> 2) + 16 * (fp >> 1);
    const int gj = (fc & 3) * 2 + (fp & 1);
    const float CS = 0.35355339059327373f * 1.4426950408889634f;

#pragma unroll
    for (int mat = 0; mat < 3; mat++) {
        const u64* Wd = g_Wd + (mat == 0 ? WD_Q : mat == 1 ? WD_K : WD_V);
        const float* bb = mat == 0 ? bq : mat == 1 ? bk : bv;
        u64 acc[8] = {0,0,0,0,0,0,0,0};
        gemm_partial(Wd, 64, c4 * 4, ys_p, 64, pq2, kq * 8, 8, acc);
        __syncthreads();           // red free from previous readers
#pragma unroll
        for (int j = 0; j < 8; j++) red[tid * 9 + j] = acc[j];
        __syncthreads();
        u64 v = gather8(red, gbase, gj);
        v = add2(v, dup2(bb[fc]));
        float2 q2 = unpk(v);
        if (mat == 1) {
            *(float2*)(g_kT + ((b * 8 + h) * 8 + dd) * 512 + s) =
                make_float2(q2.x * CS, q2.y * CS);
        } else {
            float* dst = (mat == 0 ? g_q : g_v) + ((b * 8 + h) * 512 + s) * 8 + dd;
            dst[0] = q2.x; dst[8] = q2.y;
        }
    }
}

// ---------------- attention: one (b,h,qtile-of-64) unit ----------------
// 256 threads = 16 query-groups (4 queries) x 16 key-segments (32 keys).
// Fixed-shift softmax: p = 2^(s - 32); common factor cancels in o/l.
__device__ __forceinline__ void attn_unit(int unit, u64* __restrict__ sm64) {
    float* Kt = (float*)sm64;           // [8][512]
    float* Vs = (float*)(sm64 + 2048);  // [512][8] swizzled
    const int bh  = unit >> 3;
    const int qt  = unit & 7;
    const int tid = threadIdx.x;

    {
        const float4* Ksrc = (const float4*)(g_kT + bh * 4096);
        const float4* Vsrc = (const float4*)(g_v  + bh * 4096);
        float4* Kd = (float4*)Kt;
        float4* Vd = (float4*)Vs;
        for (int i = tid; i < 1024; i += 256) {
            Kd[i] = Ksrc[i];
            Vd[i ^ ((i >> 3) & 7)] = Vsrc[i];
        }
    }
    __syncthreads();

    const int qp  = tid >> 4;    // 0..15 query group (4 queries)
    const int seg = tid & 15;    // 0..15 key segment (32 keys)
    const int q0  = qt * 64 + 4 * qp;

    // 4 queries raw (K carries the scale)
    float qs[4][8];
    {
        const float4* qg = (const float4*)(g_q + (bh * 512 + q0) * 8);
#pragma unroll
        for (int qq = 0; qq < 4; qq++) {
            float4 a = qg[2 * qq], b = qg[2 * qq + 1];
            qs[qq][0]=a.x; qs[qq][1]=a.y; qs[qq][2]=a.z; qs[qq][3]=a.w;
            qs[qq][4]=b.x; qs[qq][5]=b.y; qs[qq][6]=b.z; qs[qq][7]=b.w;
        }
    }

    const u64 NEG32 = dup2(-32.0f);
    float l[4] = {0.f, 0.f, 0.f, 0.f};
    u64 o[4][4];
#pragma unroll
    for (int qq = 0; qq < 4; qq++) { o[qq][0]=0; o[qq][1]=0; o[qq][2]=0; o[qq][3]=0; }

    for (int i = 0; i < 8; i++) {
        const int k4 = seg * 4 + 64 * i;
        u64 s[4][2];
#pragma unroll
        for (int qq = 0; qq < 4; qq++) { s[qq][0] = NEG32; s[qq][1] = NEG32; }
#pragma unroll
        for (int j = 0; j < 8; j++) {
            ulonglong2 kv = *(const ulonglong2*)(Kt + j * 512 + k4);
#pragma unroll
            for (int qq = 0; qq < 4; qq++) {
                u64 qd = dup2(qs[qq][j]);
                s[qq][0] = ffma2(qd, kv.x, s[qq][0]);
                s[qq][1] = ffma2(qd, kv.y, s[qq][1]);
            }
        }
        float p[4][4];
#pragma unroll
        for (int qq = 0; qq < 4; qq++) {
            float2 fx = unpk(s[qq][0]), fy = unpk(s[qq][1]);
            p[qq][0]=ex2f(fx.x); p[qq][1]=ex2f(fx.y);
            p[qq][2]=ex2f(fy.x); p[qq][3]=ex2f(fy.y);
            l[qq] += (p[qq][0]+p[qq][1]) + (p[qq][2]+p[qq][3]);
        }
#pragma unroll
        for (int kk = 0; kk < 4; kk++) {
            int k  = k4 + kk;
            int u0 = (2 * k) ^ (seg & 7);
            ulonglong2 va = *(const ulonglong2*)(Vs + u0 * 4);
            ulonglong2 vb = *(const ulonglong2*)(Vs + (u0 ^ 1) * 4);
#pragma unroll
            for (int qq = 0; qq < 4; qq++) {
                u64 d = dup2(p[qq][kk]);
                o[qq][0]=ffma2(d,va.x,o[qq][0]); o[qq][1]=ffma2(d,va.y,o[qq][1]);
                o[qq][2]=ffma2(d,vb.x,o[qq][2]); o[qq][3]=ffma2(d,vb.y,o[qq][3]);
            }
        }
    }

    // merge 16 key-segments: pure sums
#pragma unroll
    for (int off = 1; off < 16; off <<= 1) {
#pragma unroll
        for (int qq = 0; qq < 4; qq++) {
            l[qq] += __shfl_xor_sync(~0u, l[qq], off);
            o[qq][0] = add2(o[qq][0], __shfl_xor_sync(~0u, o[qq][0], off));
            o[qq][1] = add2(o[qq][1], __shfl_xor_sync(~0u, o[qq][1], off));
            o[qq][2] = add2(o[qq][2], __shfl_xor_sync(~0u, o[qq][2], off));
            o[qq][3] = add2(o[qq][3], __shfl_xor_sync(~0u, o[qq][3], off));
        }
    }

    if (seg == 0) {
        const int b = bh >> 3, h = bh & 7;
        const int gp = (b * 512 + q0) >> 1;
        float iA = 1.f / l[0], iB = 1.f / l[1], iC = 1.f / l[2], iD = 1.f / l[3];
        u64* op0 = g_app + gp * 64 + h * 8;
        u64* op1 = op0 + 64;
#pragma unroll
        for (int j = 0; j < 4; j++) {
            float2 a = unpk(o[0][j]), bb = unpk(o[1][j]);
            op0[2 * j]     = pack2(a.x * iA, bb.x * iB);
            op0[2 * j + 1] = pack2(a.y * iA, bb.y * iB);
            float2 c = unpk(o[2][j]), d = unpk(o[3][j]);
            op1[2 * j]     = pack2(c.x * iC, d.x * iD);
            op1[2 * j + 1] = pack2(c.y * iC, d.y * iD);
        }
    }
    __syncthreads();
}

// ---------------- tail: oproj + FFN + RK combine + next QKV (8 rows) --------
__device__ __forceinline__ void tail_unit(
        int unit, int st, int step, u64* __restrict__ sm64,
        float* __restrict__ out,
        const float* __restrict__ bq, const float* __restrict__ bk,
        const float* __restrict__ bv, const float* __restrict__ bo,
        const float* __restrict__ b1, const float* __restrict__ b2) {
    u64* app_p  = sm64;          // 256
    u64* atts_p = sm64 + 256;    // 256
    u64* z_p    = sm64 + 512;    // 256
    u64* ys_p   = sm64 + 768;    // 256
    u64* h_p    = sm64 + 1024;   // 1024
    u64* red    = sm64 + 2048;   // 2304 (256*9)

    const int tid = threadIdx.x;
    const int c4 = tid & 15, pq2 = (tid >> 4) & 1, kq = tid >> 5;
    const int fc = tid & 63, fp = tid >> 6;
    const int gbase = (fc >> 2) + 16 * (fp >> 1);
    const int gj = (fc & 3) * 2 + (fp & 1);
    const int idx = unit * 256 + tid;

    // 1. load packed attention output
    if (tid < 128)
        ((ulonglong2*)app_p)[tid] = ((const ulonglong2*)(g_app + unit * 256))[tid];
    __syncthreads();

    // 2. output projection
    {
        u64 acc[8] = {0,0,0,0,0,0,0,0};
        gemm_partial(g_Wd + WD_O, 64, c4 * 4, app_p, 64, pq2, kq * 8, 8, acc);
#pragma unroll
        for (int j = 0; j < 8; j++) red[tid * 9 + j] = acc[j];
        __syncthreads();
        u64 att = gather8(red, gbase, gj);
        att = add2(att, dup2(bo[fc]));
        atts_p[tid] = att;
        z_p[tid] = add2(att, g_ysp[idx]);
        __syncthreads();
    }

    // 3. FFN layer 1 (cols 256)
    {
        const int pq2b = fp & 1, kqb = fp >> 1;
        u64 acc[8] = {0,0,0,0,0,0,0,0};
        gemm_partial(g_Wd + WD_1, 256, fc * 4, z_p, 64, pq2b, kqb * 32, 32, acc);
        __syncthreads();
#pragma unroll
        for (int j = 0; j < 8; j++) red[tid * 9 + j] = acc[j];
        __syncthreads();
        const int wb = fc + 64 * (fp >> 1);
#pragma unroll
        for (int cl = 0; cl < 4; cl++) {
            int c = fc * 4 + cl;
            int jj = cl * 2 + (fp & 1);
            u64 hv = add2(red[wb * 9 + jj], red[(wb + 128) * 9 + jj]);
            hv = add2(hv, dup2(b1[c]));
            h_p[fp * 256 + c] = relu2(hv);
        }
        __syncthreads();
    }

    // 4. FFN layer 2 + residual + RK combine
    {
        u64 acc[8] = {0,0,0,0,0,0,0,0};
        gemm_partial(g_Wd + WD_2, 64, c4 * 4, h_p, 256, pq2, kq * 32, 32, acc);
        __syncthreads();
#pragma unroll
        for (int j = 0; j < 8; j++) red[tid * 9 + j] = acc[j];
        __syncthreads();
        u64 kv = gather8(red, gbase, gj);
        kv = add2(kv, dup2(b2[fc]));
        kv = add2(kv, atts_p[tid]);
        g_kp[st][idx] = kv;

        u64 y = g_yp[idx];
        if (st < 5) {
            for (int j = 0; j < st; j++)
                y = ffma2(dup2(d_C[st + 1][j]), g_kp[j][idx], y);
            y = ffma2(dup2(d_C[st + 1][st]), kv, y);
            g_ysp[idx] = y;
            ys_p[tid] = y;
        } else {
#pragma unroll
            for (int j = 0; j < 5; j++)
                y = ffma2(dup2(d_B[j]), g_kp[j][idx], y);
            y = ffma2(dup2(d_B[5]), kv, y);
            if (step == 3) {
                float2 f2 = unpk(y);
                int r = unit * 8 + 2 * fp;
                out[r * 64 + fc]       = f2.x;
                out[(r + 1) * 64 + fc] = f2.y;
            } else {
                g_yp[idx] = y; g_ysp[idx] = y;
                ys_p[tid] = y;
            }
        }
        __syncthreads();
    }

    // 5. next-stage QKV
    if (!(st == 5 && step == 3))
        qkv_mats(unit, ys_p, red, bq, bk, bv);
    __syncthreads();
}

// ---------------- persistent kernel ----------------
__global__ void __launch_bounds__(256, 2)
fused_ode_kernel(const float* __restrict__ x, float* __restrict__ out,
                 const float* __restrict__ Wq, const float* __restrict__ bq,
                 const float* __restrict__ Wk, const float* __restrict__ bk,
                 const float* __restrict__ Wv, const float* __restrict__ bv,
                 const float* __restrict__ Wo, const float* __restrict__ bo,
                 const float* __restrict__ W1, const float* __restrict__ b1,
                 const float* __restrict__ W2, const float* __restrict__ b2) {
    __shared__ u64 sm64[4352];
    unsigned gen = g_gen;
    const int tid = threadIdx.x;
    const unsigned nblk = gridDim.x;

    // 0. build dup'd weights in global scratch
    for (int i = blockIdx.x * 256 + tid; i < WD_N; i += nblk * 256) {
        float w;
        if (i < 16384) {
            int mat = i >> 12, e = i & 4095;
            const float* W = mat == 0 ? Wq : mat == 1 ? Wk : mat == 2 ? Wv : Wo;
            w = W[e];
        } else if (i < 32768) {
            w = W1[i - 16384];
        } else {
            w = W2[i - 32768];
        }
        g_Wd[i] = dup2(w);
    }
    gsync(gen);

    // init: y = ys = x (packed), first QKV
    for (int unit = blockIdx.x; unit < 256; unit += nblk) {
        float* xs = (float*)sm64;
        for (int i = tid; i < 128; i += 256)
            ((float4*)xs)[i] = ((const float4*)(x + unit * 512))[i];
        __syncthreads();
        {
            int p = tid >> 6, c = tid & 63;
            u64 u = pack2(xs[2 * p * 64 + c], xs[(2 * p + 1) * 64 + c]);
            __syncthreads();
            int idx = unit * 256 + tid;
            g_yp[idx] = u; g_ysp[idx] = u;
            (sm64 + 768)[tid] = u;
        }
        __syncthreads();
        qkv_mats(unit, sm64 + 768, sm64 + 2048, bq, bk, bv);
        __syncthreads();
    }
    gsync(gen);

    for (int step = 0; step < 4; ++step) {
        for (int st = 0; st < 6; ++st) {
            for (int unit = blockIdx.x; unit < 256; unit += nblk)
                attn_unit(unit, sm64);
            gsync(gen);
            for (int unit = blockIdx.x; unit < 256; unit += nblk)
                tail_unit(unit, st, step, sm64, out, bq, bk, bv, bo, b1, b2);
            if (!(step == 3 && st == 5)) gsync(gen);
        }
    }
}

// ---------------- host launcher ----------------
extern "C" void kernel_launch(void* const* d_in, const int* in_sizes, int n_in,
                              void* d_out, int out_size) {
    const float* x  = (const float*)d_in[0];
    // d_in[1] = mask: additive [B,1,S,1] broadcast over key axis -> softmax no-op
    const float* Wq = (const float*)d_in[2];
    const float* bq = (const float*)d_in[3];
    const float* Wk = (const float*)d_in[4];
    const float* bk = (const float*)d_in[5];
    const float* Wv = (const float*)d_in[6];
    const float* bv = (const float*)d_in[7];
    const float* Wo = (const float*)d_in[8];
    const float* bo = (const float*)d_in[9];
    const float* W1 = (const float*)d_in[10];
    const float* b1 = (const float*)d_in[11];
    const float* W2 = (const float*)d_in[12];
    const float* b2 = (const float*)d_in[13];
    float* out = (float*)d_out;

    int dev = 0, sms = 148;
    cudaGetDevice(&dev);
    cudaDeviceGetAttribute(&sms, cudaDevAttrMultiProcessorCount, dev);
    int nblk = sms * 2;
    if (nblk > MAXB) nblk = MAXB;

    fused_ode_kernel<<<nblk, 256>>>(x, out,
                                    Wq, bq, Wk, bk, Wv, bv,
                                    Wo, bo, W1, b1, W2, b2);
}

// round 13
// speedup vs baseline: 1.3614x; 1.3614x over previous
#include <cuda_runtime.h>

#define SEQ    512
#define NROW   2048
#define NPAIR  1024
#define NELEM  (NROW*64)
#define MAXB   512

typedef unsigned long long u64;

// ---------------- f32x2 helpers ----------------
__device__ __forceinline__ u64 ffma2(u64 a, u64 b, u64 c) {
    u64 d; asm("fma.rn.f32x2 %0, %1, %2, %3;" : "=l"(d) : "l"(a), "l"(b), "l"(c)); return d;
}
__device__ __forceinline__ u64 mul2(u64 a, u64 b) {
    u64 d; asm("mul.rn.f32x2 %0, %1, %2;" : "=l"(d) : "l"(a), "l"(b)); return d;
}
__device__ __forceinline__ u64 add2(u64 a, u64 b) {
    u64 d; asm("add.rn.f32x2 %0, %1, %2;" : "=l"(d) : "l"(a), "l"(b)); return d;
}
__device__ __forceinline__ u64 dup2(float x) {
    u64 d; asm("mov.b64 %0, {%1, %1};" : "=l"(d) : "f"(x)); return d;
}
__device__ __forceinline__ u64 pack2(float x, float y) {
    u64 d; asm("mov.b64 %0, {%1, %2};" : "=l"(d) : "f"(x), "f"(y)); return d;
}
__device__ __forceinline__ float2 unpk(u64 a) {
    float2 f; asm("mov.b64 {%0, %1}, %2;" : "=f"(f.x), "=f"(f.y) : "l"(a)); return f;
}
__device__ __forceinline__ float ex2f(float x) {
    float r; asm("ex2.approx.f32 %0, %1;" : "=f"(r) : "f"(x)); return r;
}
__device__ __forceinline__ u64 relu2(u64 a) {
    float2 f = unpk(a); return pack2(fmaxf(f.x, 0.f), fmaxf(f.y, 0.f));
}

// ---------------- device scratch ----------------
__device__ float g_q [NELEM];          // [B,H,S,8]
__device__ float g_kT[NELEM];          // [B,H,8,S]  pre-scaled by 1/sqrt(8)*log2e
__device__ float g_v [NELEM];          // [B,H,S,8]
__device__ u64 g_yp [NPAIR*64];        // y  packed: [pair][col]
__device__ u64 g_ysp[NPAIR*64];        // ys packed
__device__ u64 g_kp [6][NPAIR*64];     // k stages packed
__device__ u64 g_app[NPAIR*64];        // attn out packed [pair][h*8+d]

__device__ unsigned          g_cnt;
__device__ volatile unsigned g_gen;

__constant__ float d_C[6][5] = {
    {0.f,0.f,0.f,0.f,0.f},
    {(float)(0.25*0.25), 0.f,0.f,0.f,0.f},
    {(float)(0.25*3.0/32.0), (float)(0.25*9.0/32.0), 0.f,0.f,0.f},
    {(float)(0.25*1932.0/2197.0), (float)(0.25*-7200.0/2197.0),
     (float)(0.25*7296.0/2197.0), 0.f,0.f},
    {(float)(0.25*439.0/216.0), (float)(0.25*-8.0),
     (float)(0.25*3680.0/513.0), (float)(0.25*-845.0/4104.0), 0.f},
    {(float)(0.25*-8.0/27.0), (float)(0.25*2.0),
     (float)(0.25*-3544.0/2565.0), (float)(0.25*1859.0/4104.0),
     (float)(0.25*-11.0/40.0)}
};
__constant__ float d_B[6] = {
    (float)(0.25*16.0/135.0), 0.f,
    (float)(0.25*6656.0/12825.0),
    (float)(0.25*28561.0/56430.0),
    (float)(0.25*-9.0/50.0),
    (float)(0.25*2.0/55.0)
};

// ---------------- grid barrier (atomic counter) ----------------
__device__ __forceinline__ void gsync(unsigned& gen) {
    __syncthreads();
    if (threadIdx.x == 0) {
        __threadfence();
        if (atomicAdd(&g_cnt, 1u) == gridDim.x - 1) {
            g_cnt = 0;
            __threadfence();
            g_gen = gen + 1;
        } else {
            while (g_gen == gen) { }
            __threadfence();
        }
    }
    __syncthreads();
    gen++;
}

// ---------------- packed GEMM partial (scalar weights, inline dup) ----------
__device__ __forceinline__ void gemm_partial(
        const float* __restrict__ W, int wstride, int colbase,
        const u64* __restrict__ act, int rowlen, int pq2,
        int k0, int kn, u64* acc) {
    const u64* a0 = act + (2 * pq2) * rowlen;
    const u64* a1 = a0 + rowlen;
#pragma unroll 4
    for (int k = k0; k < k0 + kn; k++) {
        float4 w = *(const float4*)(W + k * wstride + colbase);
        u64 z0 = a0[k], z1 = a1[k];
        u64 w0 = dup2(w.x), w1 = dup2(w.y), w2 = dup2(w.z), w3 = dup2(w.w);
        acc[0] = ffma2(z0, w0, acc[0]); acc[1] = ffma2(z1, w0, acc[1]);
        acc[2] = ffma2(z0, w1, acc[2]); acc[3] = ffma2(z1, w1, acc[3]);
        acc[4] = ffma2(z0, w2, acc[4]); acc[5] = ffma2(z1, w2, acc[5]);
        acc[6] = ffma2(z0, w3, acc[6]); acc[7] = ffma2(z1, w3, acc[7]);
    }
}

// 8-way k-group gather for 64-col GEMMs (writers tid = c4 + 16*pq2 + 32*kq)
__device__ __forceinline__ u64 gather8(const u64* __restrict__ red, int base, int j) {
    u64 s = red[base * 9 + j];
#pragma unroll
    for (int kq = 1; kq < 8; kq++)
        s = add2(s, red[(base + 32 * kq) * 9 + j]);
    return s;
}

// ---------------- QKV: 3 sequential 64-col GEMMs from packed ys ----------------
// K is written PRE-SCALED by 1/sqrt(8)*log2(e) (K only feeds scores).
__device__ __forceinline__ void qkv_mats(
        int unit, const u64* __restrict__ ys_p, u64* __restrict__ red,
        const float* __restrict__ Wq, const float* __restrict__ bq,
        const float* __restrict__ Wk, const float* __restrict__ bk,
        const float* __restrict__ Wv, const float* __restrict__ bv) {
    const int tid = threadIdx.x;
    const int c4 = tid & 15, pq2 = (tid >> 4) & 1, kq = tid >> 5;
    const int fc = tid & 63, fp = tid >> 6;
    const int row0 = unit * 8 + 2 * fp;
    const int b = row0 >> 9, s = row0 & 511;
    const int h = fc >> 3, dd = fc & 7;
    const int gbase = (fc >> 2) + 16 * (fp >> 1);
    const int gj = (fc & 3) * 2 + (fp & 1);
    const float CS = 0.35355339059327373f * 1.4426950408889634f;

#pragma unroll
    for (int mat = 0; mat < 3; mat++) {
        const float* W  = mat == 0 ? Wq : mat == 1 ? Wk : Wv;
        const float* bb = mat == 0 ? bq : mat == 1 ? bk : bv;
        u64 acc[8] = {0,0,0,0,0,0,0,0};
        gemm_partial(W, 64, c4 * 4, ys_p, 64, pq2, kq * 8, 8, acc);
        __syncthreads();           // red free from previous readers
#pragma unroll
        for (int j = 0; j < 8; j++) red[tid * 9 + j] = acc[j];
        __syncthreads();
        u64 v = gather8(red, gbase, gj);
        v = add2(v, dup2(bb[fc]));
        float2 q2 = unpk(v);
        if (mat == 1) {
            *(float2*)(g_kT + ((b * 8 + h) * 8 + dd) * 512 + s) =
                make_float2(q2.x * CS, q2.y * CS);
        } else {
            float* dst = (mat == 0 ? g_q : g_v) + ((b * 8 + h) * 512 + s) * 8 + dd;
            dst[0] = q2.x; dst[8] = q2.y;
        }
    }
}

// ---------------- attention: one (b,h,qtile-of-64) unit ----------------
// 256 threads = 16 query-groups (4 queries) x 16 key-segments (32 keys).
// Fixed-shift softmax: p = 2^(s - 32); common factor cancels in o/l.
__device__ __forceinline__ void attn_unit(int unit, u64* __restrict__ sm64) {
    float* Kt = (float*)sm64;           // [8][512]
    float* Vs = (float*)(sm64 + 2048);  // [512][8] swizzled
    const int bh  = unit >> 3;
    const int qt  = unit & 7;
    const int tid = threadIdx.x;

    {
        const float4* Ksrc = (const float4*)(g_kT + bh * 4096);
        const float4* Vsrc = (const float4*)(g_v  + bh * 4096);
        float4* Kd = (float4*)Kt;
        float4* Vd = (float4*)Vs;
        for (int i = tid; i < 1024; i += 256) {
            Kd[i] = Ksrc[i];
            Vd[i ^ ((i >> 3) & 7)] = Vsrc[i];
        }
    }
    __syncthreads();

    const int qp  = tid >> 4;    // 0..15 query group (4 queries)
    const int seg = tid & 15;    // 0..15 key segment (32 keys)
    const int q0  = qt * 64 + 4 * qp;

    // 4 queries raw (K carries the scale)
    float qs[4][8];
    {
        const float4* qg = (const float4*)(g_q + (bh * 512 + q0) * 8);
#pragma unroll
        for (int qq = 0; qq < 4; qq++) {
            float4 a = qg[2 * qq], b = qg[2 * qq + 1];
            qs[qq][0]=a.x; qs[qq][1]=a.y; qs[qq][2]=a.z; qs[qq][3]=a.w;
            qs[qq][4]=b.x; qs[qq][5]=b.y; qs[qq][6]=b.z; qs[qq][7]=b.w;
        }
    }

    const u64 NEG32 = dup2(-32.0f);
    float l[4] = {0.f, 0.f, 0.f, 0.f};
    u64 o[4][4];
#pragma unroll
    for (int qq = 0; qq < 4; qq++) { o[qq][0]=0; o[qq][1]=0; o[qq][2]=0; o[qq][3]=0; }

    for (int i = 0; i < 8; i++) {
        const int k4 = seg * 4 + 64 * i;
        u64 s[4][2];
#pragma unroll
        for (int qq = 0; qq < 4; qq++) { s[qq][0] = NEG32; s[qq][1] = NEG32; }
#pragma unroll
        for (int j = 0; j < 8; j++) {
            ulonglong2 kv = *(const ulonglong2*)(Kt + j * 512 + k4);
#pragma unroll
            for (int qq = 0; qq < 4; qq++) {
                u64 qd = dup2(qs[qq][j]);
                s[qq][0] = ffma2(qd, kv.x, s[qq][0]);
                s[qq][1] = ffma2(qd, kv.y, s[qq][1]);
            }
        }
        float p[4][4];
#pragma unroll
        for (int qq = 0; qq < 4; qq++) {
            float2 fx = unpk(s[qq][0]), fy = unpk(s[qq][1]);
            p[qq][0]=ex2f(fx.x); p[qq][1]=ex2f(fx.y);
            p[qq][2]=ex2f(fy.x); p[qq][3]=ex2f(fy.y);
            l[qq] += (p[qq][0]+p[qq][1]) + (p[qq][2]+p[qq][3]);
        }
#pragma unroll
        for (int kk = 0; kk < 4; kk++) {
            int k  = k4 + kk;
            int u0 = (2 * k) ^ (seg & 7);
            ulonglong2 va = *(const ulonglong2*)(Vs + u0 * 4);
            ulonglong2 vb = *(const ulonglong2*)(Vs + (u0 ^ 1) * 4);
#pragma unroll
            for (int qq = 0; qq < 4; qq++) {
                u64 d = dup2(p[qq][kk]);
                o[qq][0]=ffma2(d,va.x,o[qq][0]); o[qq][1]=ffma2(d,va.y,o[qq][1]);
                o[qq][2]=ffma2(d,vb.x,o[qq][2]); o[qq][3]=ffma2(d,vb.y,o[qq][3]);
            }
        }
    }

    // merge 16 key-segments: pure sums
#pragma unroll
    for (int off = 1; off < 16; off <<= 1) {
#pragma unroll
        for (int qq = 0; qq < 4; qq++) {
            l[qq] += __shfl_xor_sync(~0u, l[qq], off);
            o[qq][0] = add2(o[qq][0], __shfl_xor_sync(~0u, o[qq][0], off));
            o[qq][1] = add2(o[qq][1], __shfl_xor_sync(~0u, o[qq][1], off));
            o[qq][2] = add2(o[qq][2], __shfl_xor_sync(~0u, o[qq][2], off));
            o[qq][3] = add2(o[qq][3], __shfl_xor_sync(~0u, o[qq][3], off));
        }
    }

    if (seg == 0) {
        const int b = bh >> 3, h = bh & 7;
        const int gp = (b * 512 + q0) >> 1;
        float iA = 1.f / l[0], iB = 1.f / l[1], iC = 1.f / l[2], iD = 1.f / l[3];
        u64* op0 = g_app + gp * 64 + h * 8;
        u64* op1 = op0 + 64;
#pragma unroll
        for (int j = 0; j < 4; j++) {
            float2 a = unpk(o[0][j]), bb = unpk(o[1][j]);
            op0[2 * j]     = pack2(a.x * iA, bb.x * iB);
            op0[2 * j + 1] = pack2(a.y * iA, bb.y * iB);
            float2 c = unpk(o[2][j]), d = unpk(o[3][j]);
            op1[2 * j]     = pack2(c.x * iC, d.x * iD);
            op1[2 * j + 1] = pack2(c.y * iC, d.y * iD);
        }
    }
    __syncthreads();
}

// ---------------- tail: oproj + FFN + RK combine + next QKV (8 rows) --------
__device__ __forceinline__ void tail_unit(
        int unit, int st, int step, u64* __restrict__ sm64,
        float* __restrict__ out,
        const float* __restrict__ Wq, const float* __restrict__ bq,
        const float* __restrict__ Wk, const float* __restrict__ bk,
        const float* __restrict__ Wv, const float* __restrict__ bv,
        const float* __restrict__ Wo, const float* __restrict__ bo,
        const float* __restrict__ W1, const float* __restrict__ b1,
        const float* __restrict__ W2, const float* __restrict__ b2) {
    u64* app_p  = sm64;          // 256
    u64* atts_p = sm64 + 256;    // 256
    u64* z_p    = sm64 + 512;    // 256
    u64* ys_p   = sm64 + 768;    // 256
    u64* h_p    = sm64 + 1024;   // 1024
    u64* red    = sm64 + 2048;   // 2304 (256*9)

    const int tid = threadIdx.x;
    const int c4 = tid & 15, pq2 = (tid >> 4) & 1, kq = tid >> 5;
    const int fc = tid & 63, fp = tid >> 6;
    const int gbase = (fc >> 2) + 16 * (fp >> 1);
    const int gj = (fc & 3) * 2 + (fp & 1);
    const int idx = unit * 256 + tid;

    // 1. load packed attention output
    if (tid < 128)
        ((ulonglong2*)app_p)[tid] = ((const ulonglong2*)(g_app + unit * 256))[tid];
    __syncthreads();

    // 2. output projection
    {
        u64 acc[8] = {0,0,0,0,0,0,0,0};
        gemm_partial(Wo, 64, c4 * 4, app_p, 64, pq2, kq * 8, 8, acc);
#pragma unroll
        for (int j = 0; j < 8; j++) red[tid * 9 + j] = acc[j];
        __syncthreads();
        u64 att = gather8(red, gbase, gj);
        att = add2(att, dup2(bo[fc]));
        atts_p[tid] = att;
        z_p[tid] = add2(att, g_ysp[idx]);
        __syncthreads();
    }

    // 3. FFN layer 1 (cols 256)
    {
        const int pq2b = fp & 1, kqb = fp >> 1;
        u64 acc[8] = {0,0,0,0,0,0,0,0};
        gemm_partial(W1, 256, fc * 4, z_p, 64, pq2b, kqb * 32, 32, acc);
        __syncthreads();
#pragma unroll
        for (int j = 0; j < 8; j++) red[tid * 9 + j] = acc[j];
        __syncthreads();
        const int wb = fc + 64 * (fp >> 1);
#pragma unroll
        for (int cl = 0; cl < 4; cl++) {
            int c = fc * 4 + cl;
            int jj = cl * 2 + (fp & 1);
            u64 hv = add2(red[wb * 9 + jj], red[(wb + 128) * 9 + jj]);
            hv = add2(hv, dup2(b1[c]));
            h_p[fp * 256 + c] = relu2(hv);
        }
        __syncthreads();
    }

    // 4. FFN layer 2 + residual + RK combine
    {
        u64 acc[8] = {0,0,0,0,0,0,0,0};
        gemm_partial(W2, 64, c4 * 4, h_p, 256, pq2, kq * 32, 32, acc);
        __syncthreads();
#pragma unroll
        for (int j = 0; j < 8; j++) red[tid * 9 + j] = acc[j];
        __syncthreads();
        u64 kv = gather8(red, gbase, gj);
        kv = add2(kv, dup2(b2[fc]));
        kv = add2(kv, atts_p[tid]);
        g_kp[st][idx] = kv;

        u64 y = g_yp[idx];
        if (st < 5) {
            for (int j = 0; j < st; j++)
                y = ffma2(dup2(d_C[st + 1][j]), g_kp[j][idx], y);
            y = ffma2(dup2(d_C[st + 1][st]), kv, y);
            g_ysp[idx] = y;
            ys_p[tid] = y;
        } else {
#pragma unroll
            for (int j = 0; j < 5; j++)
                y = ffma2(dup2(d_B[j]), g_kp[j][idx], y);
            y = ffma2(dup2(d_B[5]), kv, y);
            if (step == 3) {
                float2 f2 = unpk(y);
                int r = unit * 8 + 2 * fp;
                out[r * 64 + fc]       = f2.x;
                out[(r + 1) * 64 + fc] = f2.y;
            } else {
                g_yp[idx] = y; g_ysp[idx] = y;
                ys_p[tid] = y;
            }
        }
        __syncthreads();
    }

    // 5. next-stage QKV
    if (!(st == 5 && step == 3))
        qkv_mats(unit, ys_p, red, Wq, bq, Wk, bk, Wv, bv);
    __syncthreads();
}

// ---------------- persistent kernel ----------------
__global__ void __launch_bounds__(256, 2)
fused_ode_kernel(const float* __restrict__ x, float* __restrict__ out,
                 const float* __restrict__ Wq, const float* __restrict__ bq,
                 const float* __restrict__ Wk, const float* __restrict__ bk,
                 const float* __restrict__ Wv, const float* __restrict__ bv,
                 const float* __restrict__ Wo, const float* __restrict__ bo,
                 const float* __restrict__ W1, const float* __restrict__ b1,
                 const float* __restrict__ W2, const float* __restrict__ b2) {
    __shared__ u64 sm64[4352];
    unsigned gen = g_gen;
    const int tid = threadIdx.x;
    const unsigned nblk = gridDim.x;

    // init: y = ys = x (packed), first QKV
    for (int unit = blockIdx.x; unit < 256; unit += nblk) {
        float* xs = (float*)sm64;
        for (int i = tid; i < 128; i += 256)
            ((float4*)xs)[i] = ((const float4*)(x + unit * 512))[i];
        __syncthreads();
        {
            int p = tid >> 6, c = tid & 63;
            u64 u = pack2(xs[2 * p * 64 + c], xs[(2 * p + 1) * 64 + c]);
            __syncthreads();
            int idx = unit * 256 + tid;
            g_yp[idx] = u; g_ysp[idx] = u;
            (sm64 + 768)[tid] = u;
        }
        __syncthreads();
        qkv_mats(unit, sm64 + 768, sm64 + 2048, Wq, bq, Wk, bk, Wv, bv);
        __syncthreads();
    }
    gsync(gen);

    for (int step = 0; step < 4; ++step) {
        for (int st = 0; st < 6; ++st) {
            for (int unit = blockIdx.x; unit < 256; unit += nblk)
                attn_unit(unit, sm64);
            gsync(gen);
            for (int unit = blockIdx.x; unit < 256; unit += nblk)
                tail_unit(unit, st, step, sm64, out,
                          Wq, bq, Wk, bk, Wv, bv, Wo, bo, W1, b1, W2, b2);
            if (!(step == 3 && st == 5)) gsync(gen);
        }
    }
}

// ---------------- host launcher ----------------
extern "C" void kernel_launch(void* const* d_in, const int* in_sizes, int n_in,
                              void* d_out, int out_size) {
    const float* x  = (const float*)d_in[0];
    // d_in[1] = mask: additive [B,1,S,1] broadcast over key axis -> softmax no-op
    const float* Wq = (const float*)d_in[2];
    const float* bq = (const float*)d_in[3];
    const float* Wk = (const float*)d_in[4];
    const float* bk = (const float*)d_in[5];
    const float* Wv = (const float*)d_in[6];
    const float* bv = (const float*)d_in[7];
    const float* Wo = (const float*)d_in[8];
    const float* bo = (const float*)d_in[9];
    const float* W1 = (const float*)d_in[10];
    const float* b1 = (const float*)d_in[11];
    const float* W2 = (const float*)d_in[12];
    const float* b2 = (const float*)d_in[13];
    float* out = (float*)d_out;

    int dev = 0, sms = 148;
    cudaGetDevice(&dev);
    cudaDeviceGetAttribute(&sms, cudaDevAttrMultiProcessorCount, dev);
    int nblk = sms * 2;
    if (nblk > MAXB) nblk = MAXB;

    fused_ode_kernel<<<nblk, 256>>>(x, out,
                                    Wq, bq, Wk, bk, Wv, bv,
                                    Wo, bo, W1, b1, W2, b2);
}

// round 14
// speedup vs baseline: 1.3687x; 1.0054x over previous
#include <cuda_runtime.h>

#define SEQ    512
#define NROW   2048
#define NPAIR  1024
#define NELEM  (NROW*64)

typedef unsigned long long u64;

// ---------------- f32x2 helpers ----------------
__device__ __forceinline__ u64 ffma2(u64 a, u64 b, u64 c) {
    u64 d; asm("fma.rn.f32x2 %0, %1, %2, %3;" : "=l"(d) : "l"(a), "l"(b), "l"(c)); return d;
}
__device__ __forceinline__ u64 mul2(u64 a, u64 b) {
    u64 d; asm("mul.rn.f32x2 %0, %1, %2;" : "=l"(d) : "l"(a), "l"(b)); return d;
}
__device__ __forceinline__ u64 add2(u64 a, u64 b) {
    u64 d; asm("add.rn.f32x2 %0, %1, %2;" : "=l"(d) : "l"(a), "l"(b)); return d;
}
__device__ __forceinline__ u64 dup2(float x) {
    u64 d; asm("mov.b64 %0, {%1, %1};" : "=l"(d) : "f"(x)); return d;
}
__device__ __forceinline__ u64 pack2(float x, float y) {
    u64 d; asm("mov.b64 %0, {%1, %2};" : "=l"(d) : "f"(x), "f"(y)); return d;
}
__device__ __forceinline__ float2 unpk(u64 a) {
    float2 f; asm("mov.b64 {%0, %1}, %2;" : "=f"(f.x), "=f"(f.y) : "l"(a)); return f;
}
__device__ __forceinline__ float ex2f(float x) {
    float r; asm("ex2.approx.f32 %0, %1;" : "=f"(r) : "f"(x)); return r;
}
__device__ __forceinline__ u64 relu2(u64 a) {
    float2 f = unpk(a); return pack2(fmaxf(f.x, 0.f), fmaxf(f.y, 0.f));
}

// ---------------- device scratch ----------------
__device__ float g_q [NELEM];          // [B,H,S,8]
__device__ float g_kTb[2][NELEM];      // [buf][B,H,8,S] pre-scaled by 1/sqrt(8)*log2e
__device__ float g_vb [2][NELEM];      // [buf][B,H,S,8]
__device__ u64 g_yp [NPAIR*64];        // y  packed: [pair][col]
__device__ u64 g_ysp[NPAIR*64];        // ys packed
__device__ u64 g_kp [6][NPAIR*64];     // k stages packed
__device__ u64 g_app[NPAIR*64];        // attn out packed [pair][h*8+d]

// dataflow counters (reset at launch start)
__device__ unsigned g_kvrdy [25 * 4];   // [stage][batch], target 64
__device__ unsigned g_apprdy[24 * 32];  // [stage][batch*8+qt], target 8

__device__ unsigned          g_cnt;
__device__ volatile unsigned g_gen;

__constant__ float d_C[6][5] = {
    {0.f,0.f,0.f,0.f,0.f},
    {(float)(0.25*0.25), 0.f,0.f,0.f,0.f},
    {(float)(0.25*3.0/32.0), (float)(0.25*9.0/32.0), 0.f,0.f,0.f},
    {(float)(0.25*1932.0/2197.0), (float)(0.25*-7200.0/2197.0),
     (float)(0.25*7296.0/2197.0), 0.f,0.f},
    {(float)(0.25*439.0/216.0), (float)(0.25*-8.0),
     (float)(0.25*3680.0/513.0), (float)(0.25*-845.0/4104.0), 0.f},
    {(float)(0.25*-8.0/27.0), (float)(0.25*2.0),
     (float)(0.25*-3544.0/2565.0), (float)(0.25*1859.0/4104.0),
     (float)(0.25*-11.0/40.0)}
};
__constant__ float d_B[6] = {
    (float)(0.25*16.0/135.0), 0.f,
    (float)(0.25*6656.0/12825.0),
    (float)(0.25*28561.0/56430.0),
    (float)(0.25*-9.0/50.0),
    (float)(0.25*2.0/55.0)
};

// ---------------- grid barrier (init only) ----------------
__device__ __forceinline__ void gsync(unsigned& gen) {
    __syncthreads();
    if (threadIdx.x == 0) {
        __threadfence();
        if (atomicAdd(&g_cnt, 1u) == gridDim.x - 1) {
            g_cnt = 0;
            __threadfence();
            g_gen = gen + 1;
        } else {
            while (g_gen == gen) { }
            __threadfence();
        }
    }
    __syncthreads();
    gen++;
}

// ---------------- dataflow signal / wait ----------------
__device__ __forceinline__ void df_signal(unsigned* c) {
    __syncthreads();                       // all block writes done
    if (threadIdx.x == 0) {
        __threadfence();                   // release
        atomicAdd(c, 1u);
    }
}
__device__ __forceinline__ void df_wait(unsigned* c, unsigned target) {
    if (threadIdx.x == 0) {
        while (*(volatile unsigned*)c < target) { }
        __threadfence();                   // acquire
    }
    __syncthreads();
}

// ---------------- packed GEMM partial (scalar weights, inline dup) ----------
__device__ __forceinline__ void gemm_partial(
        const float* __restrict__ W, int wstride, int colbase,
        const u64* __restrict__ act, int rowlen, int pq2,
        int k0, int kn, u64* acc) {
    const u64* a0 = act + (2 * pq2) * rowlen;
    const u64* a1 = a0 + rowlen;
#pragma unroll 4
    for (int k = k0; k < k0 + kn; k++) {
        float4 w = *(const float4*)(W + k * wstride + colbase);
        u64 z0 = a0[k], z1 = a1[k];
        u64 w0 = dup2(w.x), w1 = dup2(w.y), w2 = dup2(w.z), w3 = dup2(w.w);
        acc[0] = ffma2(z0, w0, acc[0]); acc[1] = ffma2(z1, w0, acc[1]);
        acc[2] = ffma2(z0, w1, acc[2]); acc[3] = ffma2(z1, w1, acc[3]);
        acc[4] = ffma2(z0, w2, acc[4]); acc[5] = ffma2(z1, w2, acc[5]);
        acc[6] = ffma2(z0, w3, acc[6]); acc[7] = ffma2(z1, w3, acc[7]);
    }
}

// 8-way k-group gather for 64-col GEMMs (writers tid = c4 + 16*pq2 + 32*kq)
__device__ __forceinline__ u64 gather8(const u64* __restrict__ red, int base, int j) {
    u64 s = red[base * 9 + j];
#pragma unroll
    for (int kq = 1; kq < 8; kq++)
        s = add2(s, red[(base + 32 * kq) * 9 + j]);
    return s;
}

// ---------------- QKV: 3 sequential 64-col GEMMs from packed ys ----------------
// K is written PRE-SCALED by 1/sqrt(8)*log2(e); dest buffer selected by caller.
__device__ __forceinline__ void qkv_mats(
        int unit, const u64* __restrict__ ys_p, u64* __restrict__ red,
        float* __restrict__ kT, float* __restrict__ vv,
        const float* __restrict__ Wq, const float* __restrict__ bq,
        const float* __restrict__ Wk, const float* __restrict__ bk,
        const float* __restrict__ Wv, const float* __restrict__ bv) {
    const int tid = threadIdx.x;
    const int c4 = tid & 15, pq2 = (tid >> 4) & 1, kq = tid >> 5;
    const int fc = tid & 63, fp = tid >> 6;
    const int row0 = unit * 8 + 2 * fp;
    const int b = row0 >> 9, s = row0 & 511;
    const int h = fc >> 3, dd = fc & 7;
    const int gbase = (fc >> 2) + 16 * (fp >> 1);
    const int gj = (fc & 3) * 2 + (fp & 1);
    const float CS = 0.35355339059327373f * 1.4426950408889634f;

#pragma unroll
    for (int mat = 0; mat < 3; mat++) {
        const float* W  = mat == 0 ? Wq : mat == 1 ? Wk : Wv;
        const float* bb = mat == 0 ? bq : mat == 1 ? bk : bv;
        u64 acc[8] = {0,0,0,0,0,0,0,0};
        gemm_partial(W, 64, c4 * 4, ys_p, 64, pq2, kq * 8, 8, acc);
        __syncthreads();           // red free from previous readers
#pragma unroll
        for (int j = 0; j < 8; j++) red[tid * 9 + j] = acc[j];
        __syncthreads();
        u64 v = gather8(red, gbase, gj);
        v = add2(v, dup2(bb[fc]));
        float2 q2 = unpk(v);
        if (mat == 1) {
            *(float2*)(kT + ((b * 8 + h) * 8 + dd) * 512 + s) =
                make_float2(q2.x * CS, q2.y * CS);
        } else {
            float* dst = (mat == 0 ? g_q : vv) + ((b * 8 + h) * 512 + s) * 8 + dd;
            dst[0] = q2.x; dst[8] = q2.y;
        }
    }
}

// ---------------- attention: one (b,h,qtile-of-64) unit ----------------
// 256 threads = 16 query-groups (4 queries) x 16 key-segments (32 keys).
// Fixed-shift softmax: p = 2^(s - 32); common factor cancels in o/l.
__device__ __forceinline__ void attn_unit(
        int unit, u64* __restrict__ sm64,
        const float* __restrict__ kTg, const float* __restrict__ vg) {
    float* Kt = (float*)sm64;           // [8][512]
    float* Vs = (float*)(sm64 + 2048);  // [512][8] swizzled
    const int bh  = unit >> 3;
    const int qt  = unit & 7;
    const int tid = threadIdx.x;

    {
        const float4* Ksrc = (const float4*)(kTg + bh * 4096);
        const float4* Vsrc = (const float4*)(vg  + bh * 4096);
        float4* Kd = (float4*)Kt;
        float4* Vd = (float4*)Vs;
        for (int i = tid; i < 1024; i += 256) {
            Kd[i] = Ksrc[i];
            Vd[i ^ ((i >> 3) & 7)] = Vsrc[i];
        }
    }
    __syncthreads();

    const int qp  = tid >> 4;    // 0..15 query group (4 queries)
    const int seg = tid & 15;    // 0..15 key segment (32 keys)
    const int q0  = qt * 64 + 4 * qp;

    // 4 queries raw (K carries the scale)
    float qs[4][8];
    {
        const float4* qg = (const float4*)(g_q + (bh * 512 + q0) * 8);
#pragma unroll
        for (int qq = 0; qq < 4; qq++) {
            float4 a = qg[2 * qq], b = qg[2 * qq + 1];
            qs[qq][0]=a.x; qs[qq][1]=a.y; qs[qq][2]=a.z; qs[qq][3]=a.w;
            qs[qq][4]=b.x; qs[qq][5]=b.y; qs[qq][6]=b.z; qs[qq][7]=b.w;
        }
    }

    const u64 NEG32 = dup2(-32.0f);
    float l[4] = {0.f, 0.f, 0.f, 0.f};
    u64 o[4][4];
#pragma unroll
    for (int qq = 0; qq < 4; qq++) { o[qq][0]=0; o[qq][1]=0; o[qq][2]=0; o[qq][3]=0; }

    for (int i = 0; i < 8; i++) {
        const int k4 = seg * 4 + 64 * i;
        u64 s[4][2];
#pragma unroll
        for (int qq = 0; qq < 4; qq++) { s[qq][0] = NEG32; s[qq][1] = NEG32; }
#pragma unroll
        for (int j = 0; j < 8; j++) {
            ulonglong2 kv = *(const ulonglong2*)(Kt + j * 512 + k4);
#pragma unroll
            for (int qq = 0; qq < 4; qq++) {
                u64 qd = dup2(qs[qq][j]);
                s[qq][0] = ffma2(qd, kv.x, s[qq][0]);
                s[qq][1] = ffma2(qd, kv.y, s[qq][1]);
            }
        }
        float p[4][4];
#pragma unroll
        for (int qq = 0; qq < 4; qq++) {
            float2 fx = unpk(s[qq][0]), fy = unpk(s[qq][1]);
            p[qq][0]=ex2f(fx.x); p[qq][1]=ex2f(fx.y);
            p[qq][2]=ex2f(fy.x); p[qq][3]=ex2f(fy.y);
            l[qq] += (p[qq][0]+p[qq][1]) + (p[qq][2]+p[qq][3]);
        }
#pragma unroll
        for (int kk = 0; kk < 4; kk++) {
            int k  = k4 + kk;
            int u0 = (2 * k) ^ (seg & 7);
            ulonglong2 va = *(const ulonglong2*)(Vs + u0 * 4);
            ulonglong2 vb = *(const ulonglong2*)(Vs + (u0 ^ 1) * 4);
#pragma unroll
            for (int qq = 0; qq < 4; qq++) {
                u64 d = dup2(p[qq][kk]);
                o[qq][0]=ffma2(d,va.x,o[qq][0]); o[qq][1]=ffma2(d,va.y,o[qq][1]);
                o[qq][2]=ffma2(d,vb.x,o[qq][2]); o[qq][3]=ffma2(d,vb.y,o[qq][3]);
            }
        }
    }

    // merge 16 key-segments: pure sums
#pragma unroll
    for (int off = 1; off < 16; off <<= 1) {
#pragma unroll
        for (int qq = 0; qq < 4; qq++) {
            l[qq] += __shfl_xor_sync(~0u, l[qq], off);
            o[qq][0] = add2(o[qq][0], __shfl_xor_sync(~0u, o[qq][0], off));
            o[qq][1] = add2(o[qq][1], __shfl_xor_sync(~0u, o[qq][1], off));
            o[qq][2] = add2(o[qq][2], __shfl_xor_sync(~0u, o[qq][2], off));
            o[qq][3] = add2(o[qq][3], __shfl_xor_sync(~0u, o[qq][3], off));
        }
    }

    if (seg == 0) {
        const int b = bh >> 3, h = bh & 7;
        const int gp = (b * 512 + q0) >> 1;
        float iA = 1.f / l[0], iB = 1.f / l[1], iC = 1.f / l[2], iD = 1.f / l[3];
        u64* op0 = g_app + gp * 64 + h * 8;
        u64* op1 = op0 + 64;
#pragma unroll
        for (int j = 0; j < 4; j++) {
            float2 a = unpk(o[0][j]), bb = unpk(o[1][j]);
            op0[2 * j]     = pack2(a.x * iA, bb.x * iB);
            op0[2 * j + 1] = pack2(a.y * iA, bb.y * iB);
            float2 c = unpk(o[2][j]), d = unpk(o[3][j]);
            op1[2 * j]     = pack2(c.x * iC, d.x * iD);
            op1[2 * j + 1] = pack2(c.y * iC, d.y * iD);
        }
    }
    __syncthreads();
}

// ---------------- tail: oproj + FFN + RK combine + next QKV (8 rows) --------
__device__ __forceinline__ void tail_unit(
        int unit, int st, int step, u64* __restrict__ sm64,
        float* __restrict__ out,
        float* __restrict__ kT_next, float* __restrict__ v_next,
        const float* __restrict__ Wq, const float* __restrict__ bq,
        const float* __restrict__ Wk, const float* __restrict__ bk,
        const float* __restrict__ Wv, const float* __restrict__ bv,
        const float* __restrict__ Wo, const float* __restrict__ bo,
        const float* __restrict__ W1, const float* __restrict__ b1,
        const float* __restrict__ W2, const float* __restrict__ b2) {
    u64* app_p  = sm64;          // 256
    u64* atts_p = sm64 + 256;    // 256
    u64* z_p    = sm64 + 512;    // 256
    u64* ys_p   = sm64 + 768;    // 256
    u64* h_p    = sm64 + 1024;   // 1024
    u64* red    = sm64 + 2048;   // 2304 (256*9)

    const int tid = threadIdx.x;
    const int c4 = tid & 15, pq2 = (tid >> 4) & 1, kq = tid >> 5;
    const int fc = tid & 63, fp = tid >> 6;
    const int gbase = (fc >> 2) + 16 * (fp >> 1);
    const int gj = (fc & 3) * 2 + (fp & 1);
    const int idx = unit * 256 + tid;

    // 1. load packed attention output
    if (tid < 128)
        ((ulonglong2*)app_p)[tid] = ((const ulonglong2*)(g_app + unit * 256))[tid];
    __syncthreads();

    // 2. output projection
    {
        u64 acc[8] = {0,0,0,0,0,0,0,0};
        gemm_partial(Wo, 64, c4 * 4, app_p, 64, pq2, kq * 8, 8, acc);
#pragma unroll
        for (int j = 0; j < 8; j++) red[tid * 9 + j] = acc[j];
        __syncthreads();
        u64 att = gather8(red, gbase, gj);
        att = add2(att, dup2(bo[fc]));
        atts_p[tid] = att;
        z_p[tid] = add2(att, g_ysp[idx]);
        __syncthreads();
    }

    // 3. FFN layer 1 (cols 256)
    {
        const int pq2b = fp & 1, kqb = fp >> 1;
        u64 acc[8] = {0,0,0,0,0,0,0,0};
        gemm_partial(W1, 256, fc * 4, z_p, 64, pq2b, kqb * 32, 32, acc);
        __syncthreads();
#pragma unroll
        for (int j = 0; j < 8; j++) red[tid * 9 + j] = acc[j];
        __syncthreads();
        const int wb = fc + 64 * (fp >> 1);
#pragma unroll
        for (int cl = 0; cl < 4; cl++) {
            int c = fc * 4 + cl;
            int jj = cl * 2 + (fp & 1);
            u64 hv = add2(red[wb * 9 + jj], red[(wb + 128) * 9 + jj]);
            hv = add2(hv, dup2(b1[c]));
            h_p[fp * 256 + c] = relu2(hv);
        }
        __syncthreads();
    }

    // 4. FFN layer 2 + residual + RK combine
    {
        u64 acc[8] = {0,0,0,0,0,0,0,0};
        gemm_partial(W2, 64, c4 * 4, h_p, 256, pq2, kq * 32, 32, acc);
        __syncthreads();
#pragma unroll
        for (int j = 0; j < 8; j++) red[tid * 9 + j] = acc[j];
        __syncthreads();
        u64 kv = gather8(red, gbase, gj);
        kv = add2(kv, dup2(b2[fc]));
        kv = add2(kv, atts_p[tid]);
        g_kp[st][idx] = kv;

        u64 y = g_yp[idx];
        if (st < 5) {
            for (int j = 0; j < st; j++)
                y = ffma2(dup2(d_C[st + 1][j]), g_kp[j][idx], y);
            y = ffma2(dup2(d_C[st + 1][st]), kv, y);
            g_ysp[idx] = y;
            ys_p[tid] = y;
        } else {
#pragma unroll
            for (int j = 0; j < 5; j++)
                y = ffma2(dup2(d_B[j]), g_kp[j][idx], y);
            y = ffma2(dup2(d_B[5]), kv, y);
            if (step == 3) {
                float2 f2 = unpk(y);
                int r = unit * 8 + 2 * fp;
                out[r * 64 + fc]       = f2.x;
                out[(r + 1) * 64 + fc] = f2.y;
            } else {
                g_yp[idx] = y; g_ysp[idx] = y;
                ys_p[tid] = y;
            }
        }
        __syncthreads();
    }

    // 5. next-stage QKV
    if (!(st == 5 && step == 3))
        qkv_mats(unit, ys_p, red, kT_next, v_next, Wq, bq, Wk, bk, Wv, bv);
    __syncthreads();
}

// ---------------- persistent kernel: 256 blocks, dataflow sync --------------
__global__ void __launch_bounds__(256, 2)
fused_ode_kernel(const float* __restrict__ x, float* __restrict__ out,
                 const float* __restrict__ Wq, const float* __restrict__ bq,
                 const float* __restrict__ Wk, const float* __restrict__ bk,
                 const float* __restrict__ Wv, const float* __restrict__ bv,
                 const float* __restrict__ Wo, const float* __restrict__ bo,
                 const float* __restrict__ W1, const float* __restrict__ b1,
                 const float* __restrict__ W2, const float* __restrict__ b2) {
    __shared__ u64 sm64[4352];
    unsigned gen = g_gen;
    const int tid = threadIdx.x;
    const int u   = blockIdx.x;          // 0..255: attn unit u AND tail unit u
    const int b   = u >> 6;              // batch
    const int qtA = u & 7;               // attn qtile (for app signal)
    const int qtT = (u & 63) >> 3;       // tail's qtile (for app wait)

    // 0. reset dataflow counters (block 0), then grid barrier
    if (u == 0) {
        for (int i = tid; i < 25 * 4; i += 256)  g_kvrdy[i]  = 0;
        for (int i = tid; i < 24 * 32; i += 256) g_apprdy[i] = 0;
    }
    gsync(gen);

    // 1. init: y = ys = x (packed), first QKV into buffer 0
    {
        float* xs = (float*)sm64;
        for (int i = tid; i < 128; i += 256)
            ((float4*)xs)[i] = ((const float4*)(x + u * 512))[i];
        __syncthreads();
        {
            int p = tid >> 6, c = tid & 63;
            u64 uu = pack2(xs[2 * p * 64 + c], xs[(2 * p + 1) * 64 + c]);
            __syncthreads();
            int idx = u * 256 + tid;
            g_yp[idx] = uu; g_ysp[idx] = uu;
            (sm64 + 768)[tid] = uu;
        }
        __syncthreads();
        qkv_mats(u, sm64 + 768, sm64 + 2048, g_kTb[0], g_vb[0],
                 Wq, bq, Wk, bk, Wv, bv);
    }
    df_signal(&g_kvrdy[0 * 4 + b]);

    // 2. dataflow mainloop
    for (int s = 0; s < 24; ++s) {
        const int step = s / 6, st = s - step * 6;
        const int buf  = s & 1;

        df_wait(&g_kvrdy[s * 4 + b], 64u);
        attn_unit(u, sm64, g_kTb[buf], g_vb[buf]);
        df_signal(&g_apprdy[s * 32 + b * 8 + qtA]);

        df_wait(&g_apprdy[s * 32 + b * 8 + qtT], 8u);
        tail_unit(u, st, step, sm64, out, g_kTb[buf ^ 1], g_vb[buf ^ 1],
                  Wq, bq, Wk, bk, Wv, bv, Wo, bo, W1, b1, W2, b2);
        if (s < 23)
            df_signal(&g_kvrdy[(s + 1) * 4 + b]);
    }
}

// ---------------- host launcher ----------------
extern "C" void kernel_launch(void* const* d_in, const int* in_sizes, int n_in,
                              void* d_out, int out_size) {
    const float* x  = (const float*)d_in[0];
    // d_in[1] = mask: additive [B,1,S,1] broadcast over key axis -> softmax no-op
    const float* Wq = (const float*)d_in[2];
    const float* bq = (const float*)d_in[3];
    const float* Wk = (const float*)d_in[4];
    const float* bk = (const float*)d_in[5];
    const float* Wv = (const float*)d_in[6];
    const float* bv = (const float*)d_in[7];
    const float* Wo = (const float*)d_in[8];
    const float* bo = (const float*)d_in[9];
    const float* W1 = (const float*)d_in[10];
    const float* b1 = (const float*)d_in[11];
    const float* W2 = (const float*)d_in[12];
    const float* b2 = (const float*)d_in[13];
    float* out = (float*)d_out;

    fused_ode_kernel<<<256, 256>>>(x, out,
                                   Wq, bq, Wk, bk, Wv, bv,
                                   Wo, bo, W1, b1, W2, b2);
}

// round 15
// speedup vs baseline: 1.3901x; 1.0157x over previous
#include <cuda_runtime.h>

#define SEQ    512
#define NROW   2048
#define NPAIR  1024
#define NELEM  (NROW*64)
#define SMEM_BYTES 53248   // 6656 u64

typedef unsigned long long u64;

// ---------------- f32x2 helpers ----------------
__device__ __forceinline__ u64 ffma2(u64 a, u64 b, u64 c) {
    u64 d; asm("fma.rn.f32x2 %0, %1, %2, %3;" : "=l"(d) : "l"(a), "l"(b), "l"(c)); return d;
}
__device__ __forceinline__ u64 mul2(u64 a, u64 b) {
    u64 d; asm("mul.rn.f32x2 %0, %1, %2;" : "=l"(d) : "l"(a), "l"(b)); return d;
}
__device__ __forceinline__ u64 add2(u64 a, u64 b) {
    u64 d; asm("add.rn.f32x2 %0, %1, %2;" : "=l"(d) : "l"(a), "l"(b)); return d;
}
__device__ __forceinline__ u64 dup2(float x) {
    u64 d; asm("mov.b64 %0, {%1, %1};" : "=l"(d) : "f"(x)); return d;
}
__device__ __forceinline__ u64 pack2(float x, float y) {
    u64 d; asm("mov.b64 %0, {%1, %2};" : "=l"(d) : "f"(x), "f"(y)); return d;
}
__device__ __forceinline__ float2 unpk(u64 a) {
    float2 f; asm("mov.b64 {%0, %1}, %2;" : "=f"(f.x), "=f"(f.y) : "l"(a)); return f;
}
__device__ __forceinline__ float ex2f(float x) {
    float r; asm("ex2.approx.f32 %0, %1;" : "=f"(r) : "f"(x)); return r;
}
__device__ __forceinline__ u64 relu2(u64 a) {
    float2 f = unpk(a); return pack2(fmaxf(f.x, 0.f), fmaxf(f.y, 0.f));
}

// ---------------- device scratch ----------------
__device__ float g_q [NELEM];          // [B,H,S,8]
__device__ float g_kTb[2][NELEM];      // [buf][B,H,8,S] pre-scaled by 1/sqrt(8)*log2e
__device__ float g_vb [2][NELEM];      // [buf][B,H,S,8]
__device__ u64 g_yp [NPAIR*64];        // y  packed: [pair][col]
__device__ u64 g_ysp[NPAIR*64];        // ys packed
__device__ u64 g_kp [6][NPAIR*64];     // k stages packed
__device__ u64 g_app[NPAIR*64];        // attn out packed [pair][h*8+d]

// dataflow counters (reset at launch start)
__device__ unsigned g_kvrdy [25 * 4];   // [stage][batch], target 64
__device__ unsigned g_apprdy[24 * 32];  // [stage][batch*8+qt], target 8

__device__ unsigned          g_cnt;
__device__ volatile unsigned g_gen;

__constant__ float d_C[6][5] = {
    {0.f,0.f,0.f,0.f,0.f},
    {(float)(0.25*0.25), 0.f,0.f,0.f,0.f},
    {(float)(0.25*3.0/32.0), (float)(0.25*9.0/32.0), 0.f,0.f,0.f},
    {(float)(0.25*1932.0/2197.0), (float)(0.25*-7200.0/2197.0),
     (float)(0.25*7296.0/2197.0), 0.f,0.f},
    {(float)(0.25*439.0/216.0), (float)(0.25*-8.0),
     (float)(0.25*3680.0/513.0), (float)(0.25*-845.0/4104.0), 0.f},
    {(float)(0.25*-8.0/27.0), (float)(0.25*2.0),
     (float)(0.25*-3544.0/2565.0), (float)(0.25*1859.0/4104.0),
     (float)(0.25*-11.0/40.0)}
};
__constant__ float d_B[6] = {
    (float)(0.25*16.0/135.0), 0.f,
    (float)(0.25*6656.0/12825.0),
    (float)(0.25*28561.0/56430.0),
    (float)(0.25*-9.0/50.0),
    (float)(0.25*2.0/55.0)
};

// ---------------- grid barrier (init only) ----------------
__device__ __forceinline__ void gsync(unsigned& gen) {
    __syncthreads();
    if (threadIdx.x == 0) {
        __threadfence();
        if (atomicAdd(&g_cnt, 1u) == gridDim.x - 1) {
            g_cnt = 0;
            __threadfence();
            g_gen = gen + 1;
        } else {
            while (g_gen == gen) { }
            __threadfence();
        }
    }
    __syncthreads();
    gen++;
}

// ---------------- dataflow signal / wait ----------------
__device__ __forceinline__ void df_signal(unsigned* c) {
    __syncthreads();                       // all block work done (also orders smem reuse)
    if (threadIdx.x == 0) {
        __threadfence();                   // release
        atomicAdd(c, 1u);
    }
}
__device__ __forceinline__ void df_wait(unsigned* c, unsigned target) {
    if (threadIdx.x == 0) {
        while (*(volatile unsigned*)c < target) { }
        __threadfence();                   // acquire
    }
    __syncthreads();
}

// ---------------- packed GEMM partial (scalar weights, inline dup) ----------
__device__ __forceinline__ void gemm_partial(
        const float* __restrict__ W, int wstride, int colbase,
        const u64* __restrict__ act, int rowlen, int pq2,
        int k0, int kn, u64* acc) {
    const u64* a0 = act + (2 * pq2) * rowlen;
    const u64* a1 = a0 + rowlen;
#pragma unroll 4
    for (int k = k0; k < k0 + kn; k++) {
        float4 w = *(const float4*)(W + k * wstride + colbase);
        u64 z0 = a0[k], z1 = a1[k];
        u64 w0 = dup2(w.x), w1 = dup2(w.y), w2 = dup2(w.z), w3 = dup2(w.w);
        acc[0] = ffma2(z0, w0, acc[0]); acc[1] = ffma2(z1, w0, acc[1]);
        acc[2] = ffma2(z0, w1, acc[2]); acc[3] = ffma2(z1, w1, acc[3]);
        acc[4] = ffma2(z0, w2, acc[4]); acc[5] = ffma2(z1, w2, acc[5]);
        acc[6] = ffma2(z0, w3, acc[6]); acc[7] = ffma2(z1, w3, acc[7]);
    }
}

// 8-way k-group gather for 64-col GEMMs (writers tid = c4 + 16*pq2 + 32*kq)
__device__ __forceinline__ u64 gather8(const u64* __restrict__ red, int base, int j) {
    u64 s = red[base * 9 + j];
#pragma unroll
    for (int kq = 1; kq < 8; kq++)
        s = add2(s, red[(base + 32 * kq) * 9 + j]);
    return s;
}

// ---------------- QKV: 3 sequential 64-col GEMMs from packed ys ----------------
// K is written PRE-SCALED by 1/sqrt(8)*log2(e); dest buffer selected by caller.
// red0/red1: alternating reduction buffers (mat0->red0, mat1->red1, mat2->red0).
__device__ __forceinline__ void qkv_mats(
        int unit, const u64* __restrict__ ys_p,
        u64* __restrict__ red0, u64* __restrict__ red1,
        float* __restrict__ kT, float* __restrict__ vv,
        const float* __restrict__ Wq, const float* __restrict__ bq,
        const float* __restrict__ Wk, const float* __restrict__ bk,
        const float* __restrict__ Wv, const float* __restrict__ bv) {
    const int tid = threadIdx.x;
    const int c4 = tid & 15, pq2 = (tid >> 4) & 1, kq = tid >> 5;
    const int fc = tid & 63, fp = tid >> 6;
    const int row0 = unit * 8 + 2 * fp;
    const int b = row0 >> 9, s = row0 & 511;
    const int h = fc >> 3, dd = fc & 7;
    const int gbase = (fc >> 2) + 16 * (fp >> 1);
    const int gj = (fc & 3) * 2 + (fp & 1);
    const float CS = 0.35355339059327373f * 1.4426950408889634f;

#pragma unroll
    for (int mat = 0; mat < 3; mat++) {
        const float* W  = mat == 0 ? Wq : mat == 1 ? Wk : Wv;
        const float* bb = mat == 0 ? bq : mat == 1 ? bk : bv;
        u64* red = (mat == 1) ? red1 : red0;
        u64 acc[8] = {0,0,0,0,0,0,0,0};
        gemm_partial(W, 64, c4 * 4, ys_p, 64, pq2, kq * 8, 8, acc);
#pragma unroll
        for (int j = 0; j < 8; j++) red[tid * 9 + j] = acc[j];
        __syncthreads();
        u64 v = gather8(red, gbase, gj);
        v = add2(v, dup2(bb[fc]));
        float2 q2 = unpk(v);
        if (mat == 1) {
            *(float2*)(kT + ((b * 8 + h) * 8 + dd) * 512 + s) =
                make_float2(q2.x * CS, q2.y * CS);
        } else {
            float* dst = (mat == 0 ? g_q : vv) + ((b * 8 + h) * 512 + s) * 8 + dd;
            dst[0] = q2.x; dst[8] = q2.y;
        }
    }
}

// ---------------- attention: one (b,h,qtile-of-64) unit ----------------
// 256 threads = 16 query-groups (4 queries) x 16 key-segments (32 keys).
// Fixed-shift softmax: p = 2^(s - 32); common factor cancels in o/l.
// No trailing sync: caller's df_signal barrier covers smem reuse.
__device__ __forceinline__ void attn_unit(
        int unit, u64* __restrict__ sm64,
        const float* __restrict__ kTg, const float* __restrict__ vg) {
    float* Kt = (float*)sm64;           // [8][512]
    float* Vs = (float*)(sm64 + 2048);  // [512][8] swizzled
    const int bh  = unit >> 3;
    const int qt  = unit & 7;
    const int tid = threadIdx.x;

    const int qp  = tid >> 4;    // 0..15 query group (4 queries)
    const int seg = tid & 15;    // 0..15 key segment (32 keys)
    const int q0  = qt * 64 + 4 * qp;

    // q LDG first: global latency hides under the tile staging below
    float qs[4][8];
    {
        const float4* qg = (const float4*)(g_q + (bh * 512 + q0) * 8);
#pragma unroll
        for (int qq = 0; qq < 4; qq++) {
            float4 a = qg[2 * qq], b = qg[2 * qq + 1];
            qs[qq][0]=a.x; qs[qq][1]=a.y; qs[qq][2]=a.z; qs[qq][3]=a.w;
            qs[qq][4]=b.x; qs[qq][5]=b.y; qs[qq][6]=b.z; qs[qq][7]=b.w;
        }
    }

    {
        const float4* Ksrc = (const float4*)(kTg + bh * 4096);
        const float4* Vsrc = (const float4*)(vg  + bh * 4096);
        float4* Kd = (float4*)Kt;
        float4* Vd = (float4*)Vs;
        for (int i = tid; i < 1024; i += 256) {
            Kd[i] = Ksrc[i];
            Vd[i ^ ((i >> 3) & 7)] = Vsrc[i];
        }
    }
    __syncthreads();

    const u64 NEG32 = dup2(-32.0f);
    float l[4] = {0.f, 0.f, 0.f, 0.f};
    u64 o[4][4];
#pragma unroll
    for (int qq = 0; qq < 4; qq++) { o[qq][0]=0; o[qq][1]=0; o[qq][2]=0; o[qq][3]=0; }

    for (int i = 0; i < 8; i++) {
        const int k4 = seg * 4 + 64 * i;
        u64 s[4][2];
#pragma unroll
        for (int qq = 0; qq < 4; qq++) { s[qq][0] = NEG32; s[qq][1] = NEG32; }
#pragma unroll
        for (int j = 0; j < 8; j++) {
            ulonglong2 kv = *(const ulonglong2*)(Kt + j * 512 + k4);
#pragma unroll
            for (int qq = 0; qq < 4; qq++) {
                u64 qd = dup2(qs[qq][j]);
                s[qq][0] = ffma2(qd, kv.x, s[qq][0]);
                s[qq][1] = ffma2(qd, kv.y, s[qq][1]);
            }
        }
        float p[4][4];
#pragma unroll
        for (int qq = 0; qq < 4; qq++) {
            float2 fx = unpk(s[qq][0]), fy = unpk(s[qq][1]);
            p[qq][0]=ex2f(fx.x); p[qq][1]=ex2f(fx.y);
            p[qq][2]=ex2f(fy.x); p[qq][3]=ex2f(fy.y);
            l[qq] += (p[qq][0]+p[qq][1]) + (p[qq][2]+p[qq][3]);
        }
#pragma unroll
        for (int kk = 0; kk < 4; kk++) {
            int k  = k4 + kk;
            int u0 = (2 * k) ^ (seg & 7);
            ulonglong2 va = *(const ulonglong2*)(Vs + u0 * 4);
            ulonglong2 vb = *(const ulonglong2*)(Vs + (u0 ^ 1) * 4);
#pragma unroll
            for (int qq = 0; qq < 4; qq++) {
                u64 d = dup2(p[qq][kk]);
                o[qq][0]=ffma2(d,va.x,o[qq][0]); o[qq][1]=ffma2(d,va.y,o[qq][1]);
                o[qq][2]=ffma2(d,vb.x,o[qq][2]); o[qq][3]=ffma2(d,vb.y,o[qq][3]);
            }
        }
    }

    // merge 16 key-segments: pure sums
#pragma unroll
    for (int off = 1; off < 16; off <<= 1) {
#pragma unroll
        for (int qq = 0; qq < 4; qq++) {
            l[qq] += __shfl_xor_sync(~0u, l[qq], off);
            o[qq][0] = add2(o[qq][0], __shfl_xor_sync(~0u, o[qq][0], off));
            o[qq][1] = add2(o[qq][1], __shfl_xor_sync(~0u, o[qq][1], off));
            o[qq][2] = add2(o[qq][2], __shfl_xor_sync(~0u, o[qq][2], off));
            o[qq][3] = add2(o[qq][3], __shfl_xor_sync(~0u, o[qq][3], off));
        }
    }

    if (seg == 0) {
        const int b = bh >> 3, h = bh & 7;
        const int gp = (b * 512 + q0) >> 1;
        float iA = 1.f / l[0], iB = 1.f / l[1], iC = 1.f / l[2], iD = 1.f / l[3];
        u64* op0 = g_app + gp * 64 + h * 8;
        u64* op1 = op0 + 64;
#pragma unroll
        for (int j = 0; j < 4; j++) {
            float2 a = unpk(o[0][j]), bb = unpk(o[1][j]);
            op0[2 * j]     = pack2(a.x * iA, bb.x * iB);
            op0[2 * j + 1] = pack2(a.y * iA, bb.y * iB);
            float2 c = unpk(o[2][j]), d = unpk(o[3][j]);
            op1[2 * j]     = pack2(c.x * iC, d.x * iD);
            op1[2 * j + 1] = pack2(c.y * iC, d.y * iD);
        }
    }
}

// ---------------- tail: oproj + FFN + RK combine + next QKV (8 rows) --------
// Double-buffered red: oproj->A, ffn1->B, ffn2->A, qkv->B/A/B.
// Pre-write syncs removed: each buffer's previous readers are >=2 syncs back.
__device__ __forceinline__ void tail_unit(
        int unit, int st, int step, u64* __restrict__ sm64,
        float* __restrict__ out,
        float* __restrict__ kT_next, float* __restrict__ v_next,
        const float* __restrict__ Wq, const float* __restrict__ bq,
        const float* __restrict__ Wk, const float* __restrict__ bk,
        const float* __restrict__ Wv, const float* __restrict__ bv,
        const float* __restrict__ Wo, const float* __restrict__ bo,
        const float* __restrict__ W1, const float* __restrict__ b1,
        const float* __restrict__ W2, const float* __restrict__ b2) {
    u64* app_p  = sm64;          // 256
    u64* atts_p = sm64 + 256;    // 256
    u64* z_p    = sm64 + 512;    // 256
    u64* ys_p   = sm64 + 768;    // 256
    u64* h_p    = sm64 + 1024;   // 1024
    u64* redA   = sm64 + 2048;   // 2304 (256*9)
    u64* redB   = sm64 + 4352;   // 2304

    const int tid = threadIdx.x;
    const int c4 = tid & 15, pq2 = (tid >> 4) & 1, kq = tid >> 5;
    const int fc = tid & 63, fp = tid >> 6;
    const int gbase = (fc >> 2) + 16 * (fp >> 1);
    const int gj = (fc & 3) * 2 + (fp & 1);
    const int idx = unit * 256 + tid;

    // 1. load packed attention output
    if (tid < 128)
        ((ulonglong2*)app_p)[tid] = ((const ulonglong2*)(g_app + unit * 256))[tid];
    __syncthreads();

    // 2. output projection -> redA
    {
        u64 acc[8] = {0,0,0,0,0,0,0,0};
        gemm_partial(Wo, 64, c4 * 4, app_p, 64, pq2, kq * 8, 8, acc);
#pragma unroll
        for (int j = 0; j < 8; j++) redA[tid * 9 + j] = acc[j];
        __syncthreads();
        u64 att = gather8(redA, gbase, gj);
        att = add2(att, dup2(bo[fc]));
        atts_p[tid] = att;
        z_p[tid] = add2(att, g_ysp[idx]);
        __syncthreads();
    }

    // 3. FFN layer 1 (cols 256) -> redB
    {
        const int pq2b = fp & 1, kqb = fp >> 1;
        u64 acc[8] = {0,0,0,0,0,0,0,0};
        gemm_partial(W1, 256, fc * 4, z_p, 64, pq2b, kqb * 32, 32, acc);
#pragma unroll
        for (int j = 0; j < 8; j++) redB[tid * 9 + j] = acc[j];
        __syncthreads();
        const int wb = fc + 64 * (fp >> 1);
#pragma unroll
        for (int cl = 0; cl < 4; cl++) {
            int c = fc * 4 + cl;
            int jj = cl * 2 + (fp & 1);
            u64 hv = add2(redB[wb * 9 + jj], redB[(wb + 128) * 9 + jj]);
            hv = add2(hv, dup2(b1[c]));
            h_p[fp * 256 + c] = relu2(hv);
        }
        __syncthreads();
    }

    // 4. FFN layer 2 + residual + RK combine -> redA
    {
        u64 acc[8] = {0,0,0,0,0,0,0,0};
        gemm_partial(W2, 64, c4 * 4, h_p, 256, pq2, kq * 32, 32, acc);
#pragma unroll
        for (int j = 0; j < 8; j++) redA[tid * 9 + j] = acc[j];
        __syncthreads();
        u64 kv = gather8(redA, gbase, gj);
        kv = add2(kv, dup2(b2[fc]));
        kv = add2(kv, atts_p[tid]);
        g_kp[st][idx] = kv;

        u64 y = g_yp[idx];
        if (st < 5) {
            for (int j = 0; j < st; j++)
                y = ffma2(dup2(d_C[st + 1][j]), g_kp[j][idx], y);
            y = ffma2(dup2(d_C[st + 1][st]), kv, y);
            g_ysp[idx] = y;
            ys_p[tid] = y;
        } else {
#pragma unroll
            for (int j = 0; j < 5; j++)
                y = ffma2(dup2(d_B[j]), g_kp[j][idx], y);
            y = ffma2(dup2(d_B[5]), kv, y);
            if (step == 3) {
                float2 f2 = unpk(y);
                int r = unit * 8 + 2 * fp;
                out[r * 64 + fc]       = f2.x;
                out[(r + 1) * 64 + fc] = f2.y;
            } else {
                g_yp[idx] = y; g_ysp[idx] = y;
                ys_p[tid] = y;
            }
        }
        __syncthreads();   // ys_p visible before qkv reads it
    }

    // 5. next-stage QKV -> redB/redA/redB  (no trailing sync: df_signal covers)
    if (!(st == 5 && step == 3))
        qkv_mats(unit, ys_p, redB, redA, kT_next, v_next,
                 Wq, bq, Wk, bk, Wv, bv);
}

// ---------------- persistent kernel: 256 blocks, dataflow sync --------------
__global__ void __launch_bounds__(256, 2)
fused_ode_kernel(const float* __restrict__ x, float* __restrict__ out,
                 const float* __restrict__ Wq, const float* __restrict__ bq,
                 const float* __restrict__ Wk, const float* __restrict__ bk,
                 const float* __restrict__ Wv, const float* __restrict__ bv,
                 const float* __restrict__ Wo, const float* __restrict__ bo,
                 const float* __restrict__ W1, const float* __restrict__ b1,
                 const float* __restrict__ W2, const float* __restrict__ b2) {
    extern __shared__ u64 sm64[];        // 6656 u64 = 53 KB
    unsigned gen = g_gen;
    const int tid = threadIdx.x;
    const int u   = blockIdx.x;          // 0..255: attn unit u AND tail unit u
    const int b   = u >> 6;              // batch
    const int qtA = u & 7;               // attn qtile (for app signal)
    const int qtT = (u & 63) >> 3;       // tail's qtile (for app wait)

    // 0. reset dataflow counters (block 0), then grid barrier
    if (u == 0) {
        for (int i = tid; i < 25 * 4; i += 256)  g_kvrdy[i]  = 0;
        for (int i = tid; i < 24 * 32; i += 256) g_apprdy[i] = 0;
    }
    gsync(gen);

    // 1. init: y = ys = x (packed), first QKV into buffer 0
    {
        float* xs = (float*)sm64;
        for (int i = tid; i < 128; i += 256)
            ((float4*)xs)[i] = ((const float4*)(x + u * 512))[i];
        __syncthreads();
        {
            int p = tid >> 6, c = tid & 63;
            u64 uu = pack2(xs[2 * p * 64 + c], xs[(2 * p + 1) * 64 + c]);
            __syncthreads();
            int idx = u * 256 + tid;
            g_yp[idx] = uu; g_ysp[idx] = uu;
            (sm64 + 768)[tid] = uu;
        }
        __syncthreads();
        qkv_mats(u, sm64 + 768, sm64 + 2048, sm64 + 4352,
                 g_kTb[0], g_vb[0], Wq, bq, Wk, bk, Wv, bv);
    }
    df_signal(&g_kvrdy[0 * 4 + b]);

    // 2. dataflow mainloop
    for (int s = 0; s < 24; ++s) {
        const int step = s / 6, st = s - step * 6;
        const int buf  = s & 1;

        df_wait(&g_kvrdy[s * 4 + b], 64u);
        attn_unit(u, sm64, g_kTb[buf], g_vb[buf]);
        df_signal(&g_apprdy[s * 32 + b * 8 + qtA]);

        df_wait(&g_apprdy[s * 32 + b * 8 + qtT], 8u);
        tail_unit(u, st, step, sm64, out, g_kTb[buf ^ 1], g_vb[buf ^ 1],
                  Wq, bq, Wk, bk, Wv, bv, Wo, bo, W1, b1, W2, b2);
        if (s < 23)
            df_signal(&g_kvrdy[(s + 1) * 4 + b]);
    }
}

// ---------------- host launcher ----------------
extern "C" void kernel_launch(void* const* d_in, const int* in_sizes, int n_in,
                              void* d_out, int out_size) {
    const float* x  = (const float*)d_in[0];
    // d_in[1] = mask: additive [B,1,S,1] broadcast over key axis -> softmax no-op
    const float* Wq = (const float*)d_in[2];
    const float* bq = (const float*)d_in[3];
    const float* Wk = (const float*)d_in[4];
    const float* bk = (const float*)d_in[5];
    const float* Wv = (const float*)d_in[6];
    const float* bv = (const float*)d_in[7];
    const float* Wo = (const float*)d_in[8];
    const float* bo = (const float*)d_in[9];
    const float* W1 = (const float*)d_in[10];
    const float* b1 = (const float*)d_in[11];
    const float* W2 = (const float*)d_in[12];
    const float* b2 = (const float*)d_in[13];
    float* out = (float*)d_out;

    static int attr_set = 0;
    if (!attr_set) {
        cudaFuncSetAttribute(fused_ode_kernel,
                             cudaFuncAttributeMaxDynamicSharedMemorySize,
                             SMEM_BYTES);
        attr_set = 1;
    }

    fused_ode_kernel<<<256, 256, SMEM_BYTES>>>(x, out,
                                               Wq, bq, Wk, bk, Wv, bv,
                                               Wo, bo, W1, b1, W2, b2);
}

// round 16
// speedup vs baseline: 1.4583x; 1.0491x over previous
#include <cuda_runtime.h>

#define SEQ    512
#define NROW   2048
#define NPAIR  1024
#define NELEM  (NROW*64)
#define SMEM_BYTES 53248   // 6656 u64

typedef unsigned long long u64;

// ---------------- f32x2 helpers ----------------
__device__ __forceinline__ u64 ffma2(u64 a, u64 b, u64 c) {
    u64 d; asm("fma.rn.f32x2 %0, %1, %2, %3;" : "=l"(d) : "l"(a), "l"(b), "l"(c)); return d;
}
__device__ __forceinline__ u64 mul2(u64 a, u64 b) {
    u64 d; asm("mul.rn.f32x2 %0, %1, %2;" : "=l"(d) : "l"(a), "l"(b)); return d;
}
__device__ __forceinline__ u64 add2(u64 a, u64 b) {
    u64 d; asm("add.rn.f32x2 %0, %1, %2;" : "=l"(d) : "l"(a), "l"(b)); return d;
}
__device__ __forceinline__ u64 dup2(float x) {
    u64 d; asm("mov.b64 %0, {%1, %1};" : "=l"(d) : "f"(x)); return d;
}
__device__ __forceinline__ u64 pack2(float x, float y) {
    u64 d; asm("mov.b64 %0, {%1, %2};" : "=l"(d) : "f"(x), "f"(y)); return d;
}
__device__ __forceinline__ float2 unpk(u64 a) {
    float2 f; asm("mov.b64 {%0, %1}, %2;" : "=f"(f.x), "=f"(f.y) : "l"(a)); return f;
}
__device__ __forceinline__ float ex2f(float x) {
    float r; asm("ex2.approx.f32 %0, %1;" : "=f"(r) : "f"(x)); return r;
}
__device__ __forceinline__ u64 relu2(u64 a) {
    float2 f = unpk(a); return pack2(fmaxf(f.x, 0.f), fmaxf(f.y, 0.f));
}

// ---------------- device scratch ----------------
__device__ float g_q [NELEM];          // [B,H,S,8]
__device__ float g_kTb[2][NELEM];      // [buf][B,H,8,S] pre-scaled by 1/sqrt(8)*log2e
__device__ float g_vb [2][NELEM];      // [buf][B,H,S,8]
__device__ u64 g_yp [NPAIR*64];        // y  packed: [pair][col]
__device__ u64 g_ysp[NPAIR*64];        // ys packed
__device__ u64 g_kp [6][NPAIR*64];     // k stages packed
__device__ u64 g_app[NPAIR*64];        // attn out packed [pair][h*8+d]

// dataflow counters (reset at launch start)
__device__ unsigned g_kvrdy [25 * 4];   // [stage][batch], target 64
__device__ unsigned g_apprdy[24 * 32];  // [stage][batch*8+qt], target 8

__device__ unsigned          g_cnt;
__device__ volatile unsigned g_gen;

// zero-padded 6-entry RK rows: row st+1 used after stage st (st<5)
__constant__ float d_C6[6][6] = {
    {0.f,0.f,0.f,0.f,0.f,0.f},
    {(float)(0.25*0.25), 0.f,0.f,0.f,0.f,0.f},
    {(float)(0.25*3.0/32.0), (float)(0.25*9.0/32.0), 0.f,0.f,0.f,0.f},
    {(float)(0.25*1932.0/2197.0), (float)(0.25*-7200.0/2197.0),
     (float)(0.25*7296.0/2197.0), 0.f,0.f,0.f},
    {(float)(0.25*439.0/216.0), (float)(0.25*-8.0),
     (float)(0.25*3680.0/513.0), (float)(0.25*-845.0/4104.0), 0.f,0.f},
    {(float)(0.25*-8.0/27.0), (float)(0.25*2.0),
     (float)(0.25*-3544.0/2565.0), (float)(0.25*1859.0/4104.0),
     (float)(0.25*-11.0/40.0), 0.f}
};
__constant__ float d_B[6] = {
    (float)(0.25*16.0/135.0), 0.f,
    (float)(0.25*6656.0/12825.0),
    (float)(0.25*28561.0/56430.0),
    (float)(0.25*-9.0/50.0),
    (float)(0.25*2.0/55.0)
};

// ---------------- grid barrier (init only) ----------------
__device__ __forceinline__ void gsync(unsigned& gen) {
    __syncthreads();
    if (threadIdx.x == 0) {
        __threadfence();
        if (atomicAdd(&g_cnt, 1u) == gridDim.x - 1) {
            g_cnt = 0;
            __threadfence();
            g_gen = gen + 1;
        } else {
            while (g_gen == gen) { }
            __threadfence();
        }
    }
    __syncthreads();
    gen++;
}

// ---------------- dataflow signal / wait ----------------
__device__ __forceinline__ void df_signal(unsigned* c) {
    __syncthreads();                       // all block work done (also orders smem reuse)
    if (threadIdx.x == 0) {
        __threadfence();                   // release
        atomicAdd(c, 1u);
    }
}
__device__ __forceinline__ void df_wait(unsigned* c, unsigned target) {
    if (threadIdx.x == 0) {
        while (*(volatile unsigned*)c < target) { }
        __threadfence();                   // acquire
    }
    __syncthreads();
}

// ---------------- packed GEMM partial (scalar weights, inline dup) ----------
__device__ __forceinline__ void gemm_partial(
        const float* __restrict__ W, int wstride, int colbase,
        const u64* __restrict__ act, int rowlen, int pq2,
        int k0, int kn, u64* acc) {
    const u64* a0 = act + (2 * pq2) * rowlen;
    const u64* a1 = a0 + rowlen;
#pragma unroll 4
    for (int k = k0; k < k0 + kn; k++) {
        float4 w = *(const float4*)(W + k * wstride + colbase);
        u64 z0 = a0[k], z1 = a1[k];
        u64 w0 = dup2(w.x), w1 = dup2(w.y), w2 = dup2(w.z), w3 = dup2(w.w);
        acc[0] = ffma2(z0, w0, acc[0]); acc[1] = ffma2(z1, w0, acc[1]);
        acc[2] = ffma2(z0, w1, acc[2]); acc[3] = ffma2(z1, w1, acc[3]);
        acc[4] = ffma2(z0, w2, acc[4]); acc[5] = ffma2(z1, w2, acc[5]);
        acc[6] = ffma2(z0, w3, acc[6]); acc[7] = ffma2(z1, w3, acc[7]);
    }
}

// 8-way k-group gather for 64-col GEMMs (writers tid = c4 + 16*pq2 + 32*kq)
__device__ __forceinline__ u64 gather8(const u64* __restrict__ red, int base, int j) {
    u64 s = red[base * 9 + j];
#pragma unroll
    for (int kq = 1; kq < 8; kq++)
        s = add2(s, red[(base + 32 * kq) * 9 + j]);
    return s;
}

// ---------------- QKV: 3 sequential 64-col GEMMs from packed ys ----------------
// K is written PRE-SCALED by 1/sqrt(8)*log2(e); dest buffer selected by caller.
// red0/red1: alternating reduction buffers (mat0->red0, mat1->red1, mat2->red0).
__device__ __forceinline__ void qkv_mats(
        int unit, const u64* __restrict__ ys_p,
        u64* __restrict__ red0, u64* __restrict__ red1,
        float* __restrict__ kT, float* __restrict__ vv,
        const float* __restrict__ Wq, const float* __restrict__ bq,
        const float* __restrict__ Wk, const float* __restrict__ bk,
        const float* __restrict__ Wv, const float* __restrict__ bv) {
    const int tid = threadIdx.x;
    const int c4 = tid & 15, pq2 = (tid >> 4) & 1, kq = tid >> 5;
    const int fc = tid & 63, fp = tid >> 6;
    const int row0 = unit * 8 + 2 * fp;
    const int b = row0 >> 9, s = row0 & 511;
    const int h = fc >> 3, dd = fc & 7;
    const int gbase = (fc >> 2) + 16 * (fp >> 1);
    const int gj = (fc & 3) * 2 + (fp & 1);
    const float CS = 0.35355339059327373f * 1.4426950408889634f;

#pragma unroll
    for (int mat = 0; mat < 3; mat++) {
        const float* W  = mat == 0 ? Wq : mat == 1 ? Wk : Wv;
        const float* bb = mat == 0 ? bq : mat == 1 ? bk : bv;
        u64* red = (mat == 1) ? red1 : red0;
        u64 acc[8] = {0,0,0,0,0,0,0,0};
        gemm_partial(W, 64, c4 * 4, ys_p, 64, pq2, kq * 8, 8, acc);
#pragma unroll
        for (int j = 0; j < 8; j++) red[tid * 9 + j] = acc[j];
        __syncthreads();
        u64 v = gather8(red, gbase, gj);
        v = add2(v, dup2(bb[fc]));
        float2 q2 = unpk(v);
        if (mat == 1) {
            *(float2*)(kT + ((b * 8 + h) * 8 + dd) * 512 + s) =
                make_float2(q2.x * CS, q2.y * CS);
        } else {
            float* dst = (mat == 0 ? g_q : vv) + ((b * 8 + h) * 512 + s) * 8 + dd;
            dst[0] = q2.x; dst[8] = q2.y;
        }
    }
}

// ---------------- attention: one (b,h,qtile-of-64) unit ----------------
// 256 threads = 16 query-groups (4 queries) x 16 key-segments (32 keys).
// Fixed-shift softmax: p = 2^(s - 32); common factor cancels in o/l.
// No trailing sync: caller's df_signal barrier covers smem reuse.
__device__ __forceinline__ void attn_unit(
        int unit, u64* __restrict__ sm64,
        const float* __restrict__ kTg, const float* __restrict__ vg) {
    float* Kt = (float*)sm64;           // [8][512]
    float* Vs = (float*)(sm64 + 2048);  // [512][8] swizzled
    const int bh  = unit >> 3;
    const int qt  = unit & 7;
    const int tid = threadIdx.x;

    const int qp  = tid >> 4;    // 0..15 query group (4 queries)
    const int seg = tid & 15;    // 0..15 key segment (32 keys)
    const int q0  = qt * 64 + 4 * qp;

    // q LDG first: global latency hides under the tile staging below
    float qs[4][8];
    {
        const float4* qg = (const float4*)(g_q + (bh * 512 + q0) * 8);
#pragma unroll
        for (int qq = 0; qq < 4; qq++) {
            float4 a = qg[2 * qq], b = qg[2 * qq + 1];
            qs[qq][0]=a.x; qs[qq][1]=a.y; qs[qq][2]=a.z; qs[qq][3]=a.w;
            qs[qq][4]=b.x; qs[qq][5]=b.y; qs[qq][6]=b.z; qs[qq][7]=b.w;
        }
    }

    {
        const float4* Ksrc = (const float4*)(kTg + bh * 4096);
        const float4* Vsrc = (const float4*)(vg  + bh * 4096);
        float4* Kd = (float4*)Kt;
        float4* Vd = (float4*)Vs;
        for (int i = tid; i < 1024; i += 256) {
            Kd[i] = Ksrc[i];
            Vd[i ^ ((i >> 3) & 7)] = Vsrc[i];
        }
    }
    __syncthreads();

    const u64 NEG32 = dup2(-32.0f);
    float l[4] = {0.f, 0.f, 0.f, 0.f};
    u64 o[4][4];
#pragma unroll
    for (int qq = 0; qq < 4; qq++) { o[qq][0]=0; o[qq][1]=0; o[qq][2]=0; o[qq][3]=0; }

#pragma unroll 2
    for (int i = 0; i < 8; i++) {
        const int k4 = seg * 4 + 64 * i;
        u64 s[4][2];
#pragma unroll
        for (int qq = 0; qq < 4; qq++) { s[qq][0] = NEG32; s[qq][1] = NEG32; }
#pragma unroll
        for (int j = 0; j < 8; j++) {
            ulonglong2 kv = *(const ulonglong2*)(Kt + j * 512 + k4);
#pragma unroll
            for (int qq = 0; qq < 4; qq++) {
                u64 qd = dup2(qs[qq][j]);
                s[qq][0] = ffma2(qd, kv.x, s[qq][0]);
                s[qq][1] = ffma2(qd, kv.y, s[qq][1]);
            }
        }
        float p[4][4];
#pragma unroll
        for (int qq = 0; qq < 4; qq++) {
            float2 fx = unpk(s[qq][0]), fy = unpk(s[qq][1]);
            p[qq][0]=ex2f(fx.x); p[qq][1]=ex2f(fx.y);
            p[qq][2]=ex2f(fy.x); p[qq][3]=ex2f(fy.y);
            l[qq] += (p[qq][0]+p[qq][1]) + (p[qq][2]+p[qq][3]);
        }
#pragma unroll
        for (int kk = 0; kk < 4; kk++) {
            int k  = k4 + kk;
            int u0 = (2 * k) ^ (seg & 7);
            ulonglong2 va = *(const ulonglong2*)(Vs + u0 * 4);
            ulonglong2 vb = *(const ulonglong2*)(Vs + (u0 ^ 1) * 4);
#pragma unroll
            for (int qq = 0; qq < 4; qq++) {
                u64 d = dup2(p[qq][kk]);
                o[qq][0]=ffma2(d,va.x,o[qq][0]); o[qq][1]=ffma2(d,va.y,o[qq][1]);
                o[qq][2]=ffma2(d,vb.x,o[qq][2]); o[qq][3]=ffma2(d,vb.y,o[qq][3]);
            }
        }
    }

    // merge 16 key-segments: pure sums
#pragma unroll
    for (int off = 1; off < 16; off <<= 1) {
#pragma unroll
        for (int qq = 0; qq < 4; qq++) {
            l[qq] += __shfl_xor_sync(~0u, l[qq], off);
            o[qq][0] = add2(o[qq][0], __shfl_xor_sync(~0u, o[qq][0], off));
            o[qq][1] = add2(o[qq][1], __shfl_xor_sync(~0u, o[qq][1], off));
            o[qq][2] = add2(o[qq][2], __shfl_xor_sync(~0u, o[qq][2], off));
            o[qq][3] = add2(o[qq][3], __shfl_xor_sync(~0u, o[qq][3], off));
        }
    }

    if (seg == 0) {
        const int b = bh >> 3, h = bh & 7;
        const int gp = (b * 512 + q0) >> 1;
        float iA = 1.f / l[0], iB = 1.f / l[1], iC = 1.f / l[2], iD = 1.f / l[3];
        u64* op0 = g_app + gp * 64 + h * 8;
        u64* op1 = op0 + 64;
#pragma unroll
        for (int j = 0; j < 4; j++) {
            float2 a = unpk(o[0][j]), bb = unpk(o[1][j]);
            op0[2 * j]     = pack2(a.x * iA, bb.x * iB);
            op0[2 * j + 1] = pack2(a.y * iA, bb.y * iB);
            float2 c = unpk(o[2][j]), d = unpk(o[3][j]);
            op1[2 * j]     = pack2(c.x * iC, d.x * iD);
            op1[2 * j + 1] = pack2(c.y * iC, d.y * iD);
        }
    }
}

// ---------------- tail: oproj + FFN + RK combine + next QKV (8 rows) --------
// Double-buffered red: oproj->A, ffn1->B, ffn2->A, qkv->B/A/B.
__device__ __forceinline__ void tail_unit(
        int unit, int st, int step, u64* __restrict__ sm64,
        float* __restrict__ out,
        float* __restrict__ kT_next, float* __restrict__ v_next,
        const float* __restrict__ Wq, const float* __restrict__ bq,
        const float* __restrict__ Wk, const float* __restrict__ bk,
        const float* __restrict__ Wv, const float* __restrict__ bv,
        const float* __restrict__ Wo, const float* __restrict__ bo,
        const float* __restrict__ W1, const float* __restrict__ b1,
        const float* __restrict__ W2, const float* __restrict__ b2) {
    u64* app_p  = sm64;          // 256
    u64* atts_p = sm64 + 256;    // 256
    u64* z_p    = sm64 + 512;    // 256
    u64* ys_p   = sm64 + 768;    // 256
    u64* h_p    = sm64 + 1024;   // 1024
    u64* redA   = sm64 + 2048;   // 2304 (256*9)
    u64* redB   = sm64 + 4352;   // 2304

    const int tid = threadIdx.x;
    const int c4 = tid & 15, pq2 = (tid >> 4) & 1, kq = tid >> 5;
    const int fc = tid & 63, fp = tid >> 6;
    const int gbase = (fc >> 2) + 16 * (fp >> 1);
    const int gj = (fc & 3) * 2 + (fp & 1);
    const int idx = unit * 256 + tid;

    // hoisted state loads: latency hides under oproj GEMM
    const u64 ys_hoist = g_ysp[idx];
    const u64 y_hoist  = g_yp[idx];

    // 1. load packed attention output
    if (tid < 128)
        ((ulonglong2*)app_p)[tid] = ((const ulonglong2*)(g_app + unit * 256))[tid];
    __syncthreads();

    // 2. output projection -> redA
    {
        u64 acc[8] = {0,0,0,0,0,0,0,0};
        gemm_partial(Wo, 64, c4 * 4, app_p, 64, pq2, kq * 8, 8, acc);
#pragma unroll
        for (int j = 0; j < 8; j++) redA[tid * 9 + j] = acc[j];
        __syncthreads();
        u64 att = gather8(redA, gbase, gj);
        att = add2(att, dup2(bo[fc]));
        atts_p[tid] = att;
        z_p[tid] = add2(att, ys_hoist);
        __syncthreads();
    }

    // 3. FFN layer 1 (cols 256) -> redB
    {
        const int pq2b = fp & 1, kqb = fp >> 1;
        u64 acc[8] = {0,0,0,0,0,0,0,0};
        gemm_partial(W1, 256, fc * 4, z_p, 64, pq2b, kqb * 32, 32, acc);
#pragma unroll
        for (int j = 0; j < 8; j++) redB[tid * 9 + j] = acc[j];
        __syncthreads();
        const int wb = fc + 64 * (fp >> 1);
#pragma unroll
        for (int cl = 0; cl < 4; cl++) {
            int c = fc * 4 + cl;
            int jj = cl * 2 + (fp & 1);
            u64 hv = add2(redB[wb * 9 + jj], redB[(wb + 128) * 9 + jj]);
            hv = add2(hv, dup2(b1[c]));
            h_p[fp * 256 + c] = relu2(hv);
        }
        __syncthreads();
    }

    // 4. FFN layer 2 + residual + RK combine -> redA
    {
        u64 acc[8] = {0,0,0,0,0,0,0,0};
        gemm_partial(W2, 64, c4 * 4, h_p, 256, pq2, kq * 32, 32, acc);
#pragma unroll
        for (int j = 0; j < 8; j++) redA[tid * 9 + j] = acc[j];
        __syncthreads();
        u64 kv = gather8(redA, gbase, gj);
        kv = add2(kv, dup2(b2[fc]));
        kv = add2(kv, atts_p[tid]);
        g_kp[st][idx] = kv;

        // RK combine: zero-padded 6-term row, unconditional loads (full MLP).
        // g_kp[st] was just written = kv; stale entries get 0.0 coefficients.
        const float* coef = (st < 5) ? d_C6[st + 1] : d_B;
        u64 kj[6];
#pragma unroll
        for (int j = 0; j < 6; j++)
            kj[j] = (j == st) ? kv : g_kp[j][idx];
        u64 y = y_hoist;
#pragma unroll
        for (int j = 0; j < 6; j++)
            y = ffma2(dup2(coef[j]), kj[j], y);

        if (st < 5) {
            g_ysp[idx] = y;
            ys_p[tid] = y;
        } else {
            if (step == 3) {
                float2 f2 = unpk(y);
                int r = unit * 8 + 2 * fp;
                out[r * 64 + fc]       = f2.x;
                out[(r + 1) * 64 + fc] = f2.y;
            } else {
                g_yp[idx] = y; g_ysp[idx] = y;
                ys_p[tid] = y;
            }
        }
        __syncthreads();   // ys_p visible before qkv reads it
    }

    // 5. next-stage QKV -> redB/redA/redB  (no trailing sync: df_signal covers)
    if (!(st == 5 && step == 3))
        qkv_mats(unit, ys_p, redB, redA, kT_next, v_next,
                 Wq, bq, Wk, bk, Wv, bv);
}

// ---------------- persistent kernel: 256 blocks, dataflow sync --------------
__global__ void __launch_bounds__(256, 2)
fused_ode_kernel(const float* __restrict__ x, float* __restrict__ out,
                 const float* __restrict__ Wq, const float* __restrict__ bq,
                 const float* __restrict__ Wk, const float* __restrict__ bk,
                 const float* __restrict__ Wv, const float* __restrict__ bv,
                 const float* __restrict__ Wo, const float* __restrict__ bo,
                 const float* __restrict__ W1, const float* __restrict__ b1,
                 const float* __restrict__ W2, const float* __restrict__ b2) {
    extern __shared__ u64 sm64[];        // 6656 u64 = 53 KB
    unsigned gen = g_gen;
    const int tid = threadIdx.x;
    const int u   = blockIdx.x;          // 0..255: attn unit u AND tail unit u
    const int b   = u >> 6;              // batch
    const int qtA = u & 7;               // attn qtile (for app signal)
    const int qtT = (u & 63) >> 3;       // tail's qtile (for app wait)

    // 0. reset dataflow counters (block 0), then grid barrier
    if (u == 0) {
        for (int i = tid; i < 25 * 4; i += 256)  g_kvrdy[i]  = 0;
        for (int i = tid; i < 24 * 32; i += 256) g_apprdy[i] = 0;
    }
    gsync(gen);

    // 1. init: y = ys = x (packed), first QKV into buffer 0
    {
        float* xs = (float*)sm64;
        for (int i = tid; i < 128; i += 256)
            ((float4*)xs)[i] = ((const float4*)(x + u * 512))[i];
        __syncthreads();
        {
            int p = tid >> 6, c = tid & 63;
            u64 uu = pack2(xs[2 * p * 64 + c], xs[(2 * p + 1) * 64 + c]);
            __syncthreads();
            int idx = u * 256 + tid;
            g_yp[idx] = uu; g_ysp[idx] = uu;
            (sm64 + 768)[tid] = uu;
        }
        __syncthreads();
        qkv_mats(u, sm64 + 768, sm64 + 2048, sm64 + 4352,
                 g_kTb[0], g_vb[0], Wq, bq, Wk, bk, Wv, bv);
    }
    df_signal(&g_kvrdy[0 * 4 + b]);

    // 2. dataflow mainloop
    for (int s = 0; s < 24; ++s) {
        const int step = s / 6, st = s - step * 6;
        const int buf  = s & 1;

        df_wait(&g_kvrdy[s * 4 + b], 64u);
        attn_unit(u, sm64, g_kTb[buf], g_vb[buf]);
        df_signal(&g_apprdy[s * 32 + b * 8 + qtA]);

        df_wait(&g_apprdy[s * 32 + b * 8 + qtT], 8u);
        tail_unit(u, st, step, sm64, out, g_kTb[buf ^ 1], g_vb[buf ^ 1],
                  Wq, bq, Wk, bk, Wv, bv, Wo, bo, W1, b1, W2, b2);
        if (s < 23)
            df_signal(&g_kvrdy[(s + 1) * 4 + b]);
    }
}

// ---------------- host launcher ----------------
extern "C" void kernel_launch(void* const* d_in, const int* in_sizes, int n_in,
                              void* d_out, int out_size) {
    const float* x  = (const float*)d_in[0];
    // d_in[1] = mask: additive [B,1,S,1] broadcast over key axis -> softmax no-op
    const float* Wq = (const float*)d_in[2];
    const float* bq = (const float*)d_in[3];
    const float* Wk = (const float*)d_in[4];
    const float* bk = (const float*)d_in[5];
    const float* Wv = (const float*)d_in[6];
    const float* bv = (const float*)d_in[7];
    const float* Wo = (const float*)d_in[8];
    const float* bo = (const float*)d_in[9];
    const float* W1 = (const float*)d_in[10];
    const float* b1 = (const float*)d_in[11];
    const float* W2 = (const float*)d_in[12];
    const float* b2 = (const float*)d_in[13];
    float* out = (float*)d_out;

    static int attr_set = 0;
    if (!attr_set) {
        cudaFuncSetAttribute(fused_ode_kernel,
                             cudaFuncAttributeMaxDynamicSharedMemorySize,
                             SMEM_BYTES);
        attr_set = 1;
    }

    fused_ode_kernel<<<256, 256, SMEM_BYTES>>>(x, out,
                                               Wq, bq, Wk, bk, Wv, bv,
                                               Wo, bo, W1, b1, W2, b2);
}

// round 17
// speedup vs baseline: 1.4601x; 1.0012x over previous
#include <cuda_runtime.h>

#define SEQ    512
#define NROW   2048
#define NPAIR  1024
#define NELEM  (NROW*64)
#define SMEM_BYTES 71680   // 8960 u64: 2048 work + 3*2304 red

typedef unsigned long long u64;

// ---------------- f32x2 helpers ----------------
__device__ __forceinline__ u64 ffma2(u64 a, u64 b, u64 c) {
    u64 d; asm("fma.rn.f32x2 %0, %1, %2, %3;" : "=l"(d) : "l"(a), "l"(b), "l"(c)); return d;
}
__device__ __forceinline__ u64 mul2(u64 a, u64 b) {
    u64 d; asm("mul.rn.f32x2 %0, %1, %2;" : "=l"(d) : "l"(a), "l"(b)); return d;
}
__device__ __forceinline__ u64 add2(u64 a, u64 b) {
    u64 d; asm("add.rn.f32x2 %0, %1, %2;" : "=l"(d) : "l"(a), "l"(b)); return d;
}
__device__ __forceinline__ u64 dup2(float x) {
    u64 d; asm("mov.b64 %0, {%1, %1};" : "=l"(d) : "f"(x)); return d;
}
__device__ __forceinline__ u64 pack2(float x, float y) {
    u64 d; asm("mov.b64 %0, {%1, %2};" : "=l"(d) : "f"(x), "f"(y)); return d;
}
__device__ __forceinline__ float2 unpk(u64 a) {
    float2 f; asm("mov.b64 {%0, %1}, %2;" : "=f"(f.x), "=f"(f.y) : "l"(a)); return f;
}
__device__ __forceinline__ float ex2f(float x) {
    float r; asm("ex2.approx.f32 %0, %1;" : "=f"(r) : "f"(x)); return r;
}
__device__ __forceinline__ u64 relu2(u64 a) {
    float2 f = unpk(a); return pack2(fmaxf(f.x, 0.f), fmaxf(f.y, 0.f));
}

// ---------------- device scratch ----------------
__device__ float g_q [NELEM];          // [B,H,S,8]
__device__ float g_kTb[2][NELEM];      // [buf][B,H,8,S] pre-scaled by 1/sqrt(8)*log2e
__device__ float g_vb [2][NELEM];      // [buf][B,H,S,8]
__device__ u64 g_yp [NPAIR*64];        // y  packed: [pair][col]
__device__ u64 g_ysp[NPAIR*64];        // ys packed
__device__ u64 g_kp [6][NPAIR*64];     // k stages packed
__device__ u64 g_app[NPAIR*64];        // attn out packed [pair][h*8+d]

// dataflow counters (reset at launch start)
__device__ unsigned g_kvrdy [25 * 4];   // [stage][batch], target 64
__device__ unsigned g_apprdy[24 * 32];  // [stage][batch*8+qt], target 8

__device__ unsigned          g_cnt;
__device__ volatile unsigned g_gen;

// zero-padded 6-entry RK rows: row st+1 used after stage st (st<5)
__constant__ float d_C6[6][6] = {
    {0.f,0.f,0.f,0.f,0.f,0.f},
    {(float)(0.25*0.25), 0.f,0.f,0.f,0.f,0.f},
    {(float)(0.25*3.0/32.0), (float)(0.25*9.0/32.0), 0.f,0.f,0.f,0.f},
    {(float)(0.25*1932.0/2197.0), (float)(0.25*-7200.0/2197.0),
     (float)(0.25*7296.0/2197.0), 0.f,0.f,0.f},
    {(float)(0.25*439.0/216.0), (float)(0.25*-8.0),
     (float)(0.25*3680.0/513.0), (float)(0.25*-845.0/4104.0), 0.f,0.f},
    {(float)(0.25*-8.0/27.0), (float)(0.25*2.0),
     (float)(0.25*-3544.0/2565.0), (float)(0.25*1859.0/4104.0),
     (float)(0.25*-11.0/40.0), 0.f}
};
__constant__ float d_B[6] = {
    (float)(0.25*16.0/135.0), 0.f,
    (float)(0.25*6656.0/12825.0),
    (float)(0.25*28561.0/56430.0),
    (float)(0.25*-9.0/50.0),
    (float)(0.25*2.0/55.0)
};

// ---------------- grid barrier (init only) ----------------
__device__ __forceinline__ void gsync(unsigned& gen) {
    __syncthreads();
    if (threadIdx.x == 0) {
        __threadfence();
        if (atomicAdd(&g_cnt, 1u) == gridDim.x - 1) {
            g_cnt = 0;
            __threadfence();
            g_gen = gen + 1;
        } else {
            while (g_gen == gen) { }
            __threadfence();
        }
    }
    __syncthreads();
    gen++;
}

// ---------------- dataflow signal / wait ----------------
__device__ __forceinline__ void df_signal(unsigned* c) {
    __syncthreads();                       // all block work done (also orders smem reuse)
    if (threadIdx.x == 0) {
        __threadfence();                   // release
        atomicAdd(c, 1u);
    }
}
__device__ __forceinline__ void df_wait(unsigned* c, unsigned target) {
    if (threadIdx.x == 0) {
        while (*(volatile unsigned*)c < target) { }
        __threadfence();                   // acquire
    }
    __syncthreads();
}

// ---------------- packed GEMM partial (scalar weights, inline dup) ----------
__device__ __forceinline__ void gemm_partial(
        const float* __restrict__ W, int wstride, int colbase,
        const u64* __restrict__ act, int rowlen, int pq2,
        int k0, int kn, u64* acc) {
    const u64* a0 = act + (2 * pq2) * rowlen;
    const u64* a1 = a0 + rowlen;
#pragma unroll 4
    for (int k = k0; k < k0 + kn; k++) {
        float4 w = *(const float4*)(W + k * wstride + colbase);
        u64 z0 = a0[k], z1 = a1[k];
        u64 w0 = dup2(w.x), w1 = dup2(w.y), w2 = dup2(w.z), w3 = dup2(w.w);
        acc[0] = ffma2(z0, w0, acc[0]); acc[1] = ffma2(z1, w0, acc[1]);
        acc[2] = ffma2(z0, w1, acc[2]); acc[3] = ffma2(z1, w1, acc[3]);
        acc[4] = ffma2(z0, w2, acc[4]); acc[5] = ffma2(z1, w2, acc[5]);
        acc[6] = ffma2(z0, w3, acc[6]); acc[7] = ffma2(z1, w3, acc[7]);
    }
}

// 8-way k-group gather for 64-col GEMMs (writers tid = c4 + 16*pq2 + 32*kq)
__device__ __forceinline__ u64 gather8(const u64* __restrict__ red, int base, int j) {
    u64 s = red[base * 9 + j];
#pragma unroll
    for (int kq = 1; kq < 8; kq++)
        s = add2(s, red[(base + 32 * kq) * 9 + j]);
    return s;
}

// ---------------- QKV: 3 GEMMs, ONE sync, 3 gathers ----------------
// K is written PRE-SCALED by 1/sqrt(8)*log2(e); dest buffer selected by caller.
// red[mat]: one reduction buffer per matrix, so the three weight streams
// pipeline back-to-back with no intervening barrier.
__device__ __forceinline__ void qkv_mats(
        int unit, const u64* __restrict__ ys_p,
        u64* __restrict__ red0, u64* __restrict__ red1, u64* __restrict__ red2,
        float* __restrict__ kT, float* __restrict__ vv,
        const float* __restrict__ Wq, const float* __restrict__ bq,
        const float* __restrict__ Wk, const float* __restrict__ bk,
        const float* __restrict__ Wv, const float* __restrict__ bv) {
    const int tid = threadIdx.x;
    const int c4 = tid & 15, pq2 = (tid >> 4) & 1, kq = tid >> 5;
    const int fc = tid & 63, fp = tid >> 6;
    const int row0 = unit * 8 + 2 * fp;
    const int b = row0 >> 9, s = row0 & 511;
    const int h = fc >> 3, dd = fc & 7;
    const int gbase = (fc >> 2) + 16 * (fp >> 1);
    const int gj = (fc & 3) * 2 + (fp & 1);
    const float CS = 0.35355339059327373f * 1.4426950408889634f;
    u64* reds[3] = {red0, red1, red2};

#pragma unroll
    for (int mat = 0; mat < 3; mat++) {
        const float* W = mat == 0 ? Wq : mat == 1 ? Wk : Wv;
        u64* red = reds[mat];
        u64 acc[8] = {0,0,0,0,0,0,0,0};
        gemm_partial(W, 64, c4 * 4, ys_p, 64, pq2, kq * 8, 8, acc);
#pragma unroll
        for (int j = 0; j < 8; j++) red[tid * 9 + j] = acc[j];
    }
    __syncthreads();

#pragma unroll
    for (int mat = 0; mat < 3; mat++) {
        const float* bb = mat == 0 ? bq : mat == 1 ? bk : bv;
        u64 v = gather8(reds[mat], gbase, gj);
        v = add2(v, dup2(bb[fc]));
        float2 q2 = unpk(v);
        if (mat == 1) {
            *(float2*)(kT + ((b * 8 + h) * 8 + dd) * 512 + s) =
                make_float2(q2.x * CS, q2.y * CS);
        } else {
            float* dst = (mat == 0 ? g_q : vv) + ((b * 8 + h) * 512 + s) * 8 + dd;
            dst[0] = q2.x; dst[8] = q2.y;
        }
    }
}

// ---------------- attention: one (b,h,qtile-of-64) unit ----------------
// 256 threads = 16 query-groups (4 queries) x 16 key-segments (32 keys).
// Fixed-shift softmax: p = 2^(s - 32); common factor cancels in o/l.
// No trailing sync: caller's df_signal barrier covers smem reuse.
__device__ __forceinline__ void attn_unit(
        int unit, u64* __restrict__ sm64,
        const float* __restrict__ kTg, const float* __restrict__ vg) {
    float* Kt = (float*)sm64;           // [8][512]
    float* Vs = (float*)(sm64 + 2048);  // [512][8] swizzled
    const int bh  = unit >> 3;
    const int qt  = unit & 7;
    const int tid = threadIdx.x;

    const int qp  = tid >> 4;    // 0..15 query group (4 queries)
    const int seg = tid & 15;    // 0..15 key segment (32 keys)
    const int q0  = qt * 64 + 4 * qp;

    // q LDG first: global latency hides under the tile staging below
    float qs[4][8];
    {
        const float4* qg = (const float4*)(g_q + (bh * 512 + q0) * 8);
#pragma unroll
        for (int qq = 0; qq < 4; qq++) {
            float4 a = qg[2 * qq], b = qg[2 * qq + 1];
            qs[qq][0]=a.x; qs[qq][1]=a.y; qs[qq][2]=a.z; qs[qq][3]=a.w;
            qs[qq][4]=b.x; qs[qq][5]=b.y; qs[qq][6]=b.z; qs[qq][7]=b.w;
        }
    }

    {
        const float4* Ksrc = (const float4*)(kTg + bh * 4096);
        const float4* Vsrc = (const float4*)(vg  + bh * 4096);
        float4* Kd = (float4*)Kt;
        float4* Vd = (float4*)Vs;
        for (int i = tid; i < 1024; i += 256) {
            Kd[i] = Ksrc[i];
            Vd[i ^ ((i >> 3) & 7)] = Vsrc[i];
        }
    }
    __syncthreads();

    const u64 NEG32 = dup2(-32.0f);
    float l[4] = {0.f, 0.f, 0.f, 0.f};
    u64 o[4][4];
#pragma unroll
    for (int qq = 0; qq < 4; qq++) { o[qq][0]=0; o[qq][1]=0; o[qq][2]=0; o[qq][3]=0; }

#pragma unroll 2
    for (int i = 0; i < 8; i++) {
        const int k4 = seg * 4 + 64 * i;
        u64 s[4][2];
#pragma unroll
        for (int qq = 0; qq < 4; qq++) { s[qq][0] = NEG32; s[qq][1] = NEG32; }
#pragma unroll
        for (int j = 0; j < 8; j++) {
            ulonglong2 kv = *(const ulonglong2*)(Kt + j * 512 + k4);
#pragma unroll
            for (int qq = 0; qq < 4; qq++) {
                u64 qd = dup2(qs[qq][j]);
                s[qq][0] = ffma2(qd, kv.x, s[qq][0]);
                s[qq][1] = ffma2(qd, kv.y, s[qq][1]);
            }
        }
        float p[4][4];
#pragma unroll
        for (int qq = 0; qq < 4; qq++) {
            float2 fx = unpk(s[qq][0]), fy = unpk(s[qq][1]);
            p[qq][0]=ex2f(fx.x); p[qq][1]=ex2f(fx.y);
            p[qq][2]=ex2f(fy.x); p[qq][3]=ex2f(fy.y);
            l[qq] += (p[qq][0]+p[qq][1]) + (p[qq][2]+p[qq][3]);
        }
#pragma unroll
        for (int kk = 0; kk < 4; kk++) {
            int k  = k4 + kk;
            int u0 = (2 * k) ^ (seg & 7);
            ulonglong2 va = *(const ulonglong2*)(Vs + u0 * 4);
            ulonglong2 vb = *(const ulonglong2*)(Vs + (u0 ^ 1) * 4);
#pragma unroll
            for (int qq = 0; qq < 4; qq++) {
                u64 d = dup2(p[qq][kk]);
                o[qq][0]=ffma2(d,va.x,o[qq][0]); o[qq][1]=ffma2(d,va.y,o[qq][1]);
                o[qq][2]=ffma2(d,vb.x,o[qq][2]); o[qq][3]=ffma2(d,vb.y,o[qq][3]);
            }
        }
    }

    // merge 16 key-segments: pure sums
#pragma unroll
    for (int off = 1; off < 16; off <<= 1) {
#pragma unroll
        for (int qq = 0; qq < 4; qq++) {
            l[qq] += __shfl_xor_sync(~0u, l[qq], off);
            o[qq][0] = add2(o[qq][0], __shfl_xor_sync(~0u, o[qq][0], off));
            o[qq][1] = add2(o[qq][1], __shfl_xor_sync(~0u, o[qq][1], off));
            o[qq][2] = add2(o[qq][2], __shfl_xor_sync(~0u, o[qq][2], off));
            o[qq][3] = add2(o[qq][3], __shfl_xor_sync(~0u, o[qq][3], off));
        }
    }

    if (seg == 0) {
        const int b = bh >> 3, h = bh & 7;
        const int gp = (b * 512 + q0) >> 1;
        float iA = 1.f / l[0], iB = 1.f / l[1], iC = 1.f / l[2], iD = 1.f / l[3];
        u64* op0 = g_app + gp * 64 + h * 8;
        u64* op1 = op0 + 64;
#pragma unroll
        for (int j = 0; j < 4; j++) {
            float2 a = unpk(o[0][j]), bb = unpk(o[1][j]);
            op0[2 * j]     = pack2(a.x * iA, bb.x * iB);
            op0[2 * j + 1] = pack2(a.y * iA, bb.y * iB);
            float2 c = unpk(o[2][j]), d = unpk(o[3][j]);
            op1[2 * j]     = pack2(c.x * iC, d.x * iD);
            op1[2 * j + 1] = pack2(c.y * iC, d.y * iD);
        }
    }
}

// ---------------- tail: oproj + FFN + RK combine + next QKV (8 rows) --------
__device__ __forceinline__ void tail_unit(
        int unit, int st, int step, u64* __restrict__ sm64,
        float* __restrict__ out,
        float* __restrict__ kT_next, float* __restrict__ v_next,
        const float* __restrict__ Wq, const float* __restrict__ bq,
        const float* __restrict__ Wk, const float* __restrict__ bk,
        const float* __restrict__ Wv, const float* __restrict__ bv,
        const float* __restrict__ Wo, const float* __restrict__ bo,
        const float* __restrict__ W1, const float* __restrict__ b1,
        const float* __restrict__ W2, const float* __restrict__ b2) {
    u64* app_p  = sm64;          // 256
    u64* atts_p = sm64 + 256;    // 256
    u64* z_p    = sm64 + 512;    // 256
    u64* ys_p   = sm64 + 768;    // 256
    u64* h_p    = sm64 + 1024;   // 1024
    u64* redA   = sm64 + 2048;   // 2304 (256*9)
    u64* redB   = sm64 + 4352;   // 2304
    u64* redC   = sm64 + 6656;   // 2304

    const int tid = threadIdx.x;
    const int c4 = tid & 15, pq2 = (tid >> 4) & 1, kq = tid >> 5;
    const int fc = tid & 63, fp = tid >> 6;
    const int gbase = (fc >> 2) + 16 * (fp >> 1);
    const int gj = (fc & 3) * 2 + (fp & 1);
    const int idx = unit * 256 + tid;

    // hoisted state loads: latency hides under oproj GEMM
    const u64 ys_hoist = g_ysp[idx];
    const u64 y_hoist  = g_yp[idx];

    // 1. load packed attention output
    if (tid < 128)
        ((ulonglong2*)app_p)[tid] = ((const ulonglong2*)(g_app + unit * 256))[tid];
    __syncthreads();

    // 2. output projection -> redA
    {
        u64 acc[8] = {0,0,0,0,0,0,0,0};
        gemm_partial(Wo, 64, c4 * 4, app_p, 64, pq2, kq * 8, 8, acc);
#pragma unroll
        for (int j = 0; j < 8; j++) redA[tid * 9 + j] = acc[j];
        __syncthreads();
        u64 att = gather8(redA, gbase, gj);
        att = add2(att, dup2(bo[fc]));
        atts_p[tid] = att;
        z_p[tid] = add2(att, ys_hoist);
        __syncthreads();
    }

    // 3. FFN layer 1 (cols 256) -> redB
    {
        const int pq2b = fp & 1, kqb = fp >> 1;
        u64 acc[8] = {0,0,0,0,0,0,0,0};
        gemm_partial(W1, 256, fc * 4, z_p, 64, pq2b, kqb * 32, 32, acc);
#pragma unroll
        for (int j = 0; j < 8; j++) redB[tid * 9 + j] = acc[j];
        __syncthreads();
        const int wb = fc + 64 * (fp >> 1);
#pragma unroll
        for (int cl = 0; cl < 4; cl++) {
            int c = fc * 4 + cl;
            int jj = cl * 2 + (fp & 1);
            u64 hv = add2(redB[wb * 9 + jj], redB[(wb + 128) * 9 + jj]);
            hv = add2(hv, dup2(b1[c]));
            h_p[fp * 256 + c] = relu2(hv);
        }
        __syncthreads();
    }

    // 4. FFN layer 2 + residual + RK combine -> redA
    {
        u64 acc[8] = {0,0,0,0,0,0,0,0};
        gemm_partial(W2, 64, c4 * 4, h_p, 256, pq2, kq * 32, 32, acc);
#pragma unroll
        for (int j = 0; j < 8; j++) redA[tid * 9 + j] = acc[j];
        __syncthreads();
        u64 kv = gather8(redA, gbase, gj);
        kv = add2(kv, dup2(b2[fc]));
        kv = add2(kv, atts_p[tid]);
        g_kp[st][idx] = kv;

        // RK combine: zero-padded 6-term row, unconditional loads (full MLP).
        const float* coef = (st < 5) ? d_C6[st + 1] : d_B;
        u64 kj[6];
#pragma unroll
        for (int j = 0; j < 6; j++)
            kj[j] = (j == st) ? kv : g_kp[j][idx];
        u64 y = y_hoist;
#pragma unroll
        for (int j = 0; j < 6; j++)
            y = ffma2(dup2(coef[j]), kj[j], y);

        if (st < 5) {
            g_ysp[idx] = y;
            ys_p[tid] = y;
        } else {
            if (step == 3) {
                float2 f2 = unpk(y);
                int r = unit * 8 + 2 * fp;
                out[r * 64 + fc]       = f2.x;
                out[(r + 1) * 64 + fc] = f2.y;
            } else {
                g_yp[idx] = y; g_ysp[idx] = y;
                ys_p[tid] = y;
            }
        }
        __syncthreads();   // ys_p visible before qkv reads it
    }

    // 5. next-stage QKV (3 GEMMs, one internal sync; df_signal covers tail)
    if (!(st == 5 && step == 3))
        qkv_mats(unit, ys_p, redA, redB, redC, kT_next, v_next,
                 Wq, bq, Wk, bk, Wv, bv);
}

// ---------------- persistent kernel: 256 blocks, dataflow sync --------------
__global__ void __launch_bounds__(256, 2)
fused_ode_kernel(const float* __restrict__ x, float* __restrict__ out,
                 const float* __restrict__ Wq, const float* __restrict__ bq,
                 const float* __restrict__ Wk, const float* __restrict__ bk,
                 const float* __restrict__ Wv, const float* __restrict__ bv,
                 const float* __restrict__ Wo, const float* __restrict__ bo,
                 const float* __restrict__ W1, const float* __restrict__ b1,
                 const float* __restrict__ W2, const float* __restrict__ b2) {
    extern __shared__ u64 sm64[];        // 8960 u64 = 70 KB
    unsigned gen = g_gen;
    const int tid = threadIdx.x;
    const int u   = blockIdx.x;          // 0..255: attn unit u AND tail unit u
    const int b   = u >> 6;              // batch
    const int qtA = u & 7;               // attn qtile (for app signal)
    const int qtT = (u & 63) >> 3;       // tail's qtile (for app wait)

    // 0. reset dataflow counters (block 0), then grid barrier
    if (u == 0) {
        for (int i = tid; i < 25 * 4; i += 256)  g_kvrdy[i]  = 0;
        for (int i = tid; i < 24 * 32; i += 256) g_apprdy[i] = 0;
    }
    gsync(gen);

    // 1. init: y = ys = x (packed), first QKV into buffer 0
    {
        float* xs = (float*)sm64;
        for (int i = tid; i < 128; i += 256)
            ((float4*)xs)[i] = ((const float4*)(x + u * 512))[i];
        __syncthreads();
        {
            int p = tid >> 6, c = tid & 63;
            u64 uu = pack2(xs[2 * p * 64 + c], xs[(2 * p + 1) * 64 + c]);
            __syncthreads();
            int idx = u * 256 + tid;
            g_yp[idx] = uu; g_ysp[idx] = uu;
            (sm64 + 768)[tid] = uu;
        }
        __syncthreads();
        qkv_mats(u, sm64 + 768, sm64 + 2048, sm64 + 4352, sm64 + 6656,
                 g_kTb[0], g_vb[0], Wq, bq, Wk, bk, Wv, bv);
    }
    df_signal(&g_kvrdy[0 * 4 + b]);

    // 2. dataflow mainloop
    for (int s = 0; s < 24; ++s) {
        const int step = s / 6, st = s - step * 6;
        const int buf  = s & 1;

        df_wait(&g_kvrdy[s * 4 + b], 64u);
        attn_unit(u, sm64, g_kTb[buf], g_vb[buf]);
        df_signal(&g_apprdy[s * 32 + b * 8 + qtA]);

        df_wait(&g_apprdy[s * 32 + b * 8 + qtT], 8u);
        tail_unit(u, st, step, sm64, out, g_kTb[buf ^ 1], g_vb[buf ^ 1],
                  Wq, bq, Wk, bk, Wv, bv, Wo, bo, W1, b1, W2, b2);
        if (s < 23)
            df_signal(&g_kvrdy[(s + 1) * 4 + b]);
    }
}

// ---------------- host launcher ----------------
extern "C" void kernel_launch(void* const* d_in, const int* in_sizes, int n_in,
                              void* d_out, int out_size) {
    const float* x  = (const float*)d_in[0];
    // d_in[1] = mask: additive [B,1,S,1] broadcast over key axis -> softmax no-op
    const float* Wq = (const float*)d_in[2];
    const float* bq = (const float*)d_in[3];
    const float* Wk = (const float*)d_in[4];
    const float* bk = (const float*)d_in[5];
    const float* Wv = (const float*)d_in[6];
    const float* bv = (const float*)d_in[7];
    const float* Wo = (const float*)d_in[8];
    const float* bo = (const float*)d_in[9];
    const float* W1 = (const float*)d_in[10];
    const float* b1 = (const float*)d_in[11];
    const float* W2 = (const float*)d_in[12];
    const float* b2 = (const float*)d_in[13];
    float* out = (float*)d_out;

    static int attr_set = 0;
    if (!attr_set) {
        cudaFuncSetAttribute(fused_ode_kernel,
                             cudaFuncAttributeMaxDynamicSharedMemorySize,
                             SMEM_BYTES);
        attr_set = 1;
    }

    fused_ode_kernel<<<256, 256, SMEM_BYTES>>>(x, out,
                                               Wq, bq, Wk, bk, Wv, bv,
                                               Wo, bo, W1, b1, W2, b2);
}